// round 1
// baseline (speedup 1.0000x reference)
#include <cuda_runtime.h>
#include <math.h>

#define BDIM 2
#define CDIM 512
#define NSP  4096
#define GROUPS 32
#define CPG  16

// ---- static scratch (module-load allocation; no cudaMalloc) ----
__device__ float g_hn[(size_t)BDIM * CDIM * NSP];
__device__ float g_q [(size_t)BDIM * CDIM * NSP];
__device__ float g_k [(size_t)BDIM * CDIM * NSP];
__device__ float g_v [(size_t)BDIM * CDIM * NSP];
__device__ float g_o [(size_t)BDIM * CDIM * NSP];
__device__ float g_s [(size_t)BDIM * NSP * NSP];   // 128 MiB scores/attn

// ---------------- reductions ----------------
__device__ __forceinline__ float blockReduceSum(float v, float* sh) {
    #pragma unroll
    for (int o = 16; o; o >>= 1) v += __shfl_down_sync(0xffffffffu, v, o);
    int lane = threadIdx.x & 31, wid = threadIdx.x >> 5;
    if (lane == 0) sh[wid] = v;
    __syncthreads();
    int nw = blockDim.x >> 5;
    v = (threadIdx.x < nw) ? sh[threadIdx.x] : 0.f;
    if (wid == 0) {
        #pragma unroll
        for (int o = 16; o; o >>= 1) v += __shfl_down_sync(0xffffffffu, v, o);
    }
    return v;  // valid in thread 0
}

__device__ __forceinline__ float blockReduceMax(float v, float* sh) {
    #pragma unroll
    for (int o = 16; o; o >>= 1) v = fmaxf(v, __shfl_down_sync(0xffffffffu, v, o));
    int lane = threadIdx.x & 31, wid = threadIdx.x >> 5;
    if (lane == 0) sh[wid] = v;
    __syncthreads();
    int nw = blockDim.x >> 5;
    v = (threadIdx.x < nw) ? sh[threadIdx.x] : -3.0e38f;
    if (wid == 0) {
        #pragma unroll
        for (int o = 16; o; o >>= 1) v = fmaxf(v, __shfl_down_sync(0xffffffffu, v, o));
    }
    return v;
}

// ---------------- GroupNorm ----------------
__global__ void gn_kernel(const float* __restrict__ x,
                          const float* __restrict__ w,
                          const float* __restrict__ bb,
                          float* __restrict__ hn) {
    __shared__ float sh[32];
    __shared__ float s_mean, s_rstd;
    int blk = blockIdx.x;
    int b = blk / GROUPS, g = blk % GROUPS;
    size_t base = ((size_t)b * CDIM + (size_t)g * CPG) * NSP;
    const float* xp = x + base;
    const int TOT = CPG * NSP;  // 65536

    float s = 0.f, ss = 0.f;
    for (int i = threadIdx.x; i < TOT; i += blockDim.x) {
        float v = xp[i];
        s += v; ss += v * v;
    }
    float tot = blockReduceSum(s, sh);
    __syncthreads();
    float tot2 = blockReduceSum(ss, sh);
    if (threadIdx.x == 0) {
        float mean = tot / (float)TOT;
        float var  = tot2 / (float)TOT - mean * mean;
        s_mean = mean;
        s_rstd = rsqrtf(var + 1e-6f);
    }
    __syncthreads();
    float mean = s_mean, rstd = s_rstd;
    float* hp = hn + base;
    for (int i = threadIdx.x; i < TOT; i += blockDim.x) {
        int c = g * CPG + (i >> 12);
        hp[i] = (xp[i] - mean) * rstd * w[c] + bb[c];
    }
}

// ---------------- tiled fp32 GEMM ----------------
// C[m,n] = sum_k opA(m,k) * opB(k,n) ; opA = TA ? A[k*lda+m] : A[m*lda+k]
//                                      opB = TB ? B[n*ldb+k] : B[k*ldb+n]
// EPI: 0 = +bias[m], 1 = *scale, 2 = none, 3 = +bias[m] + resid
#define TBM 64
#define TBN 64
#define TBK 16

template<int TA, int TB, int EPI>
__global__ void __launch_bounds__(256)
gemm_kernel(const float* __restrict__ A, const float* __restrict__ B,
            float* __restrict__ C, int M, int N, int K,
            int lda, int ldb, int ldc,
            size_t sA, size_t sB, size_t sC,
            const float* __restrict__ bias, float scale,
            const float* __restrict__ resid) {
    int bz = blockIdx.z;
    A += sA * (size_t)bz;
    B += sB * (size_t)bz;
    C += sC * (size_t)bz;

    int m0 = blockIdx.y * TBM;
    int n0 = blockIdx.x * TBN;

    __shared__ float As[TBK][TBM + 4];
    __shared__ float Bs[TBK][TBN + 4];

    int t  = threadIdx.x;
    int tx = t & 15, ty = t >> 4;

    float acc[4][4];
    #pragma unroll
    for (int i = 0; i < 4; i++)
        #pragma unroll
        for (int j = 0; j < 4; j++) acc[i][j] = 0.f;

    for (int kb = 0; kb < K; kb += TBK) {
        if (TA == 0) {
            int mm = t >> 2, kk = (t & 3) << 2;
            float4 v = *reinterpret_cast<const float4*>(
                &A[(size_t)(m0 + mm) * lda + kb + kk]);
            As[kk + 0][mm] = v.x; As[kk + 1][mm] = v.y;
            As[kk + 2][mm] = v.z; As[kk + 3][mm] = v.w;
        } else {
            int kk = t >> 4, mm = (t & 15) << 2;
            float4 v = *reinterpret_cast<const float4*>(
                &A[(size_t)(kb + kk) * lda + m0 + mm]);
            As[kk][mm + 0] = v.x; As[kk][mm + 1] = v.y;
            As[kk][mm + 2] = v.z; As[kk][mm + 3] = v.w;
        }
        if (TB == 0) {
            int kk = t >> 4, nn = (t & 15) << 2;
            float4 v = *reinterpret_cast<const float4*>(
                &B[(size_t)(kb + kk) * ldb + n0 + nn]);
            Bs[kk][nn + 0] = v.x; Bs[kk][nn + 1] = v.y;
            Bs[kk][nn + 2] = v.z; Bs[kk][nn + 3] = v.w;
        } else {
            int nn = t >> 2, kk = (t & 3) << 2;
            float4 v = *reinterpret_cast<const float4*>(
                &B[(size_t)(n0 + nn) * ldb + kb + kk]);
            Bs[kk + 0][nn] = v.x; Bs[kk + 1][nn] = v.y;
            Bs[kk + 2][nn] = v.z; Bs[kk + 3][nn] = v.w;
        }
        __syncthreads();

        #pragma unroll
        for (int k = 0; k < TBK; ++k) {
            float a[4], bv[4];
            #pragma unroll
            for (int i = 0; i < 4; i++) a[i] = As[k][ty * 4 + i];
            #pragma unroll
            for (int j = 0; j < 4; j++) bv[j] = Bs[k][tx * 4 + j];
            #pragma unroll
            for (int i = 0; i < 4; i++)
                #pragma unroll
                for (int j = 0; j < 4; j++)
                    acc[i][j] = fmaf(a[i], bv[j], acc[i][j]);
        }
        __syncthreads();
    }

    #pragma unroll
    for (int i = 0; i < 4; i++) {
        int m = m0 + ty * 4 + i;
        float bval = (EPI == 0 || EPI == 3) ? bias[m] : 0.f;
        #pragma unroll
        for (int j = 0; j < 4; j++) {
            int n = n0 + tx * 4 + j;
            float v = acc[i][j];
            if (EPI == 1) v *= scale;
            v += bval;
            if (EPI == 3) v += resid[sC * (size_t)bz + (size_t)m * ldc + n];
            C[(size_t)m * ldc + n] = v;
        }
    }
}

// ---------------- row softmax over NSP ----------------
__global__ void softmax_kernel(float* __restrict__ s) {
    __shared__ float sh[32];
    __shared__ float s_bc;
    size_t row = blockIdx.x;
    float* p = s + row * (size_t)NSP;
    int tid = threadIdx.x;

    float m = -3.0e38f;
    for (int i = tid; i < NSP; i += blockDim.x) m = fmaxf(m, p[i]);
    m = blockReduceMax(m, sh);
    if (tid == 0) s_bc = m;
    __syncthreads();
    m = s_bc;
    __syncthreads();

    float sum = 0.f;
    for (int i = tid; i < NSP; i += blockDim.x) {
        float e = __expf(p[i] - m);
        p[i] = e;
        sum += e;
    }
    sum = blockReduceSum(sum, sh);
    if (tid == 0) s_bc = 1.f / sum;
    __syncthreads();
    float inv = s_bc;
    for (int i = tid; i < NSP; i += blockDim.x) p[i] *= inv;
}

// ---------------- launcher ----------------
extern "C" void kernel_launch(void* const* d_in, const int* in_sizes, int n_in,
                              void* d_out, int out_size) {
    const float* x    = (const float*)d_in[0];
    const float* gn_w = (const float*)d_in[1];
    const float* gn_b = (const float*)d_in[2];
    const float* wq   = (const float*)d_in[3];
    const float* bq   = (const float*)d_in[4];
    const float* wk   = (const float*)d_in[5];
    const float* bk   = (const float*)d_in[6];
    const float* wv   = (const float*)d_in[7];
    const float* bv   = (const float*)d_in[8];
    const float* wp   = (const float*)d_in[9];
    const float* bp   = (const float*)d_in[10];
    float* out = (float*)d_out;

    float *hn, *q, *k, *v, *o, *s;
    cudaGetSymbolAddress((void**)&hn, g_hn);
    cudaGetSymbolAddress((void**)&q,  g_q);
    cudaGetSymbolAddress((void**)&k,  g_k);
    cudaGetSymbolAddress((void**)&v,  g_v);
    cudaGetSymbolAddress((void**)&o,  g_o);
    cudaGetSymbolAddress((void**)&s,  g_s);

    const size_t sCN = (size_t)CDIM * NSP;      // per-batch [C,N] stride
    const size_t sNN = (size_t)NSP * NSP;       // per-batch [N,N] stride
    const float attn_scale = 0.04419417382415922f;  // 1/sqrt(512)

    gn_kernel<<<BDIM * GROUPS, 512>>>(x, gn_w, gn_b, hn);

    dim3 blk(256);
    dim3 gp(NSP / TBN, CDIM / TBM, BDIM);   // 64 x 8 x 2
    dim3 gs(NSP / TBN, NSP / TBM, BDIM);    // 64 x 64 x 2

    // Q/K/V projections: W[512,512] @ hn[512,4096] + b
    gemm_kernel<0,0,0><<<gp, blk>>>(wq, hn, q, CDIM, NSP, CDIM, CDIM, NSP, NSP,
                                    0, sCN, sCN, bq, 1.f, nullptr);
    gemm_kernel<0,0,0><<<gp, blk>>>(wk, hn, k, CDIM, NSP, CDIM, CDIM, NSP, NSP,
                                    0, sCN, sCN, bk, 1.f, nullptr);
    gemm_kernel<0,0,0><<<gp, blk>>>(wv, hn, v, CDIM, NSP, CDIM, CDIM, NSP, NSP,
                                    0, sCN, sCN, bv, 1.f, nullptr);

    // scores[i,j] = (1/sqrt(C)) * sum_c q[c,i] k[c,j]   (TA=1)
    gemm_kernel<1,0,1><<<gs, blk>>>(q, k, s, NSP, NSP, CDIM, NSP, NSP, NSP,
                                    sCN, sCN, sNN, nullptr, attn_scale, nullptr);

    softmax_kernel<<<BDIM * NSP, 256>>>(s);

    // o[c,i] = sum_j v[c,j] attn[i,j]   (TB=1)
    gemm_kernel<0,1,2><<<gp, blk>>>(v, s, o, CDIM, NSP, NSP, NSP, NSP, NSP,
                                    sCN, sNN, sCN, nullptr, 1.f, nullptr);

    // out = x + wp @ o + bp
    gemm_kernel<0,0,3><<<gp, blk>>>(wp, o, out, CDIM, NSP, CDIM, CDIM, NSP, NSP,
                                    0, sCN, sCN, bp, 1.f, x);
}

// round 3
// speedup vs baseline: 2.8082x; 2.8082x over previous
#include <cuda_runtime.h>
#include <cstdint>
#include <math.h>

#define BDIM 2
#define CDIM 512
#define NSP  4096
#define GROUPS 32
#define CPG  16

// ---- static scratch ----
__device__ float g_hn[(size_t)BDIM * CDIM * NSP];
__device__ float g_q [(size_t)BDIM * CDIM * NSP];
__device__ float g_k [(size_t)BDIM * CDIM * NSP];
__device__ float g_v [(size_t)BDIM * CDIM * NSP];
__device__ float g_o [(size_t)BDIM * CDIM * NSP];
__device__ float g_s [(size_t)BDIM * NSP * NSP];   // 128 MiB scores/attn

// ---------------- reductions ----------------
__device__ __forceinline__ float blockReduceSum(float v, float* sh) {
    #pragma unroll
    for (int o = 16; o; o >>= 1) v += __shfl_down_sync(0xffffffffu, v, o);
    int lane = threadIdx.x & 31, wid = threadIdx.x >> 5;
    if (lane == 0) sh[wid] = v;
    __syncthreads();
    int nw = blockDim.x >> 5;
    v = (threadIdx.x < nw) ? sh[threadIdx.x] : 0.f;
    if (wid == 0) {
        #pragma unroll
        for (int o = 16; o; o >>= 1) v += __shfl_down_sync(0xffffffffu, v, o);
    }
    return v;
}

__device__ __forceinline__ float blockReduceMax(float v, float* sh) {
    #pragma unroll
    for (int o = 16; o; o >>= 1) v = fmaxf(v, __shfl_down_sync(0xffffffffu, v, o));
    int lane = threadIdx.x & 31, wid = threadIdx.x >> 5;
    if (lane == 0) sh[wid] = v;
    __syncthreads();
    int nw = blockDim.x >> 5;
    v = (threadIdx.x < nw) ? sh[threadIdx.x] : -3.0e38f;
    if (wid == 0) {
        #pragma unroll
        for (int o = 16; o; o >>= 1) v = fmaxf(v, __shfl_down_sync(0xffffffffu, v, o));
    }
    return v;
}

// ---------------- GroupNorm ----------------
__global__ void gn_kernel(const float* __restrict__ x,
                          const float* __restrict__ w,
                          const float* __restrict__ bb,
                          float* __restrict__ hn) {
    __shared__ float sh[32];
    __shared__ float s_mean, s_rstd;
    int blk = blockIdx.x;
    int b = blk / GROUPS, g = blk % GROUPS;
    size_t base = ((size_t)b * CDIM + (size_t)g * CPG) * NSP;
    const float* xp = x + base;
    const int TOT = CPG * NSP;

    float s = 0.f, ss = 0.f;
    for (int i = threadIdx.x; i < TOT; i += blockDim.x) {
        float v = xp[i];
        s += v; ss += v * v;
    }
    float tot = blockReduceSum(s, sh);
    __syncthreads();
    float tot2 = blockReduceSum(ss, sh);
    if (threadIdx.x == 0) {
        float mean = tot / (float)TOT;
        float var  = tot2 / (float)TOT - mean * mean;
        s_mean = mean;
        s_rstd = rsqrtf(var + 1e-6f);
    }
    __syncthreads();
    float mean = s_mean, rstd = s_rstd;
    float* hp = hn + base;
    for (int i = threadIdx.x; i < TOT; i += blockDim.x) {
        int c = g * CPG + (i >> 12);
        hp[i] = (xp[i] - mean) * rstd * w[c] + bb[c];
    }
}

// ---------------- tf32 tensor-core GEMM ----------------
__device__ __forceinline__ uint32_t f2tf(float x) {
    uint32_t u;
    asm("cvt.rna.tf32.f32 %0, %1;" : "=r"(u) : "f"(x));
    return u;
}

__device__ __forceinline__ void mma_tf32(float* c, const uint32_t* a, const uint32_t* b) {
    asm volatile(
        "mma.sync.aligned.m16n8k8.row.col.f32.tf32.tf32.f32 "
        "{%0,%1,%2,%3}, {%4,%5,%6,%7}, {%8,%9}, {%0,%1,%2,%3};"
        : "+f"(c[0]), "+f"(c[1]), "+f"(c[2]), "+f"(c[3])
        : "r"(a[0]), "r"(a[1]), "r"(a[2]), "r"(a[3]), "r"(b[0]), "r"(b[1]));
}

// C[m,n] = sum_k opA(m,k)*opB(k,n); opA = TA? A[k*lda+m] : A[m*lda+k]
//                                   opB = TB? B[n*ldb+k] : B[k*ldb+n]
// EPI: 0 = +bias[m], 1 = *scale, 2 = none, 3 = +bias[m]+resid
#define BM 128
#define BN 128
#define BK 16

template<int TA, int TB, int EPI>
__global__ void __launch_bounds__(256, 2)
gemm_tc(const float* __restrict__ A, const float* __restrict__ B,
        float* __restrict__ C, int K,
        int lda, int ldb, int ldc,
        size_t sA, size_t sB, size_t sC,
        const float* __restrict__ bias, float scale,
        const float* __restrict__ resid) {
    int bz = blockIdx.z;
    A += sA * (size_t)bz;
    B += sB * (size_t)bz;
    C += sC * (size_t)bz;

    const int m0 = blockIdx.y * BM;
    const int n0 = blockIdx.x * BN;

    // smem layouts (all conflict-free for fragment reads):
    //  TA==0: As[m*20 + k]   (m-major, pad 20)   TA==1: As[k*136 + m]
    //  TB==0: Bs[k*136 + n]                      TB==1: Bs[n*20 + k]
    constexpr int ASZ = TA ? (BK * 136) : (BM * 20);
    constexpr int BSZ = TB ? (BN * 20) : (BK * 136);
    __shared__ uint32_t As[ASZ];
    __shared__ uint32_t Bs[BSZ];

    const int t = threadIdx.x;
    const int w = t >> 5, lane = t & 31;
    const int wm = w >> 2, wn = w & 3;        // 2 x 4 warp grid
    const int gr = lane >> 2, gc = lane & 3;  // mma thread groups

    float acc[4][4][4];
    #pragma unroll
    for (int i = 0; i < 4; i++)
        #pragma unroll
        for (int j = 0; j < 4; j++)
            #pragma unroll
            for (int r = 0; r < 4; r++) acc[i][j][r] = 0.f;

    for (int kb = 0; kb < K; kb += BK) {
        // ---- load A tile ----
        #pragma unroll
        for (int it = 0; it < 2; it++) {
            int q = t + it * 256;
            if (TA == 0) {
                int r = q >> 2, kq = (q & 3) << 2;
                float4 v = *reinterpret_cast<const float4*>(
                    &A[(size_t)(m0 + r) * lda + kb + kq]);
                uint32_t* d = &As[r * 20 + kq];
                d[0] = f2tf(v.x); d[1] = f2tf(v.y); d[2] = f2tf(v.z); d[3] = f2tf(v.w);
            } else {
                int kr = q >> 5, mq = (q & 31) << 2;
                float4 v = *reinterpret_cast<const float4*>(
                    &A[(size_t)(kb + kr) * lda + m0 + mq]);
                uint32_t* d = &As[kr * 136 + mq];
                d[0] = f2tf(v.x); d[1] = f2tf(v.y); d[2] = f2tf(v.z); d[3] = f2tf(v.w);
            }
        }
        // ---- load B tile ----
        #pragma unroll
        for (int it = 0; it < 2; it++) {
            int q = t + it * 256;
            if (TB == 0) {
                int kr = q >> 5, nq = (q & 31) << 2;
                float4 v = *reinterpret_cast<const float4*>(
                    &B[(size_t)(kb + kr) * ldb + n0 + nq]);
                uint32_t* d = &Bs[kr * 136 + nq];
                d[0] = f2tf(v.x); d[1] = f2tf(v.y); d[2] = f2tf(v.z); d[3] = f2tf(v.w);
            } else {
                int nr = q >> 2, kq = (q & 3) << 2;
                float4 v = *reinterpret_cast<const float4*>(
                    &B[(size_t)(n0 + nr) * ldb + kb + kq]);
                uint32_t* d = &Bs[nr * 20 + kq];
                d[0] = f2tf(v.x); d[1] = f2tf(v.y); d[2] = f2tf(v.z); d[3] = f2tf(v.w);
            }
        }
        __syncthreads();

        #pragma unroll
        for (int kk = 0; kk < BK; kk += 8) {
            uint32_t af[4][4];
            #pragma unroll
            for (int mt = 0; mt < 4; mt++) {
                int row = wm * 64 + mt * 16 + gr;
                int k = kk + gc;
                if (TA == 0) {
                    af[mt][0] = As[(row)     * 20 + k];
                    af[mt][1] = As[(row + 8) * 20 + k];
                    af[mt][2] = As[(row)     * 20 + k + 4];
                    af[mt][3] = As[(row + 8) * 20 + k + 4];
                } else {
                    af[mt][0] = As[(k)     * 136 + row];
                    af[mt][1] = As[(k)     * 136 + row + 8];
                    af[mt][2] = As[(k + 4) * 136 + row];
                    af[mt][3] = As[(k + 4) * 136 + row + 8];
                }
            }
            uint32_t bf[4][2];
            #pragma unroll
            for (int nt = 0; nt < 4; nt++) {
                int col = wn * 32 + nt * 8 + gr;
                int k = kk + gc;
                if (TB == 0) {
                    bf[nt][0] = Bs[(k)     * 136 + col];
                    bf[nt][1] = Bs[(k + 4) * 136 + col];
                } else {
                    bf[nt][0] = Bs[col * 20 + k];
                    bf[nt][1] = Bs[col * 20 + k + 4];
                }
            }
            #pragma unroll
            for (int mt = 0; mt < 4; mt++)
                #pragma unroll
                for (int nt = 0; nt < 4; nt++)
                    mma_tf32(acc[mt][nt], af[mt], bf[nt]);
        }
        __syncthreads();
    }

    // ---- epilogue ----
    #pragma unroll
    for (int mt = 0; mt < 4; mt++) {
        int mA = m0 + wm * 64 + mt * 16 + gr;
        int mB = mA + 8;
        float biasA = (EPI == 0 || EPI == 3) ? bias[mA] : 0.f;
        float biasB = (EPI == 0 || EPI == 3) ? bias[mB] : 0.f;
        #pragma unroll
        for (int nt = 0; nt < 4; nt++) {
            int n = n0 + wn * 32 + nt * 8 + 2 * gc;
            float v0 = acc[mt][nt][0], v1 = acc[mt][nt][1];
            float v2 = acc[mt][nt][2], v3 = acc[mt][nt][3];
            if (EPI == 1) { v0 *= scale; v1 *= scale; v2 *= scale; v3 *= scale; }
            v0 += biasA; v1 += biasA; v2 += biasB; v3 += biasB;
            if (EPI == 3) {
                const float* rp = resid + sC * (size_t)bz;
                float2 r0 = *reinterpret_cast<const float2*>(&rp[(size_t)mA * ldc + n]);
                float2 r1 = *reinterpret_cast<const float2*>(&rp[(size_t)mB * ldc + n]);
                v0 += r0.x; v1 += r0.y; v2 += r1.x; v3 += r1.y;
            }
            *reinterpret_cast<float2*>(&C[(size_t)mA * ldc + n]) = make_float2(v0, v1);
            *reinterpret_cast<float2*>(&C[(size_t)mB * ldc + n]) = make_float2(v2, v3);
        }
    }
}

// ---------------- register-resident row softmax ----------------
__global__ void __launch_bounds__(512)
softmax_kernel(float* __restrict__ s) {
    __shared__ float sh[32];
    __shared__ float s_bc;
    size_t row = blockIdx.x;
    float* p = s + row * (size_t)NSP;
    int tid = threadIdx.x;

    float4 v0 = *reinterpret_cast<const float4*>(&p[tid * 8]);
    float4 v1 = *reinterpret_cast<const float4*>(&p[tid * 8 + 4]);

    float m = fmaxf(fmaxf(fmaxf(v0.x, v0.y), fmaxf(v0.z, v0.w)),
                    fmaxf(fmaxf(v1.x, v1.y), fmaxf(v1.z, v1.w)));
    m = blockReduceMax(m, sh);
    if (tid == 0) s_bc = m;
    __syncthreads();
    m = s_bc;
    __syncthreads();

    v0.x = __expf(v0.x - m); v0.y = __expf(v0.y - m);
    v0.z = __expf(v0.z - m); v0.w = __expf(v0.w - m);
    v1.x = __expf(v1.x - m); v1.y = __expf(v1.y - m);
    v1.z = __expf(v1.z - m); v1.w = __expf(v1.w - m);
    float sum = v0.x + v0.y + v0.z + v0.w + v1.x + v1.y + v1.z + v1.w;
    sum = blockReduceSum(sum, sh);
    if (tid == 0) s_bc = 1.f / sum;
    __syncthreads();
    float inv = s_bc;

    v0.x *= inv; v0.y *= inv; v0.z *= inv; v0.w *= inv;
    v1.x *= inv; v1.y *= inv; v1.z *= inv; v1.w *= inv;
    *reinterpret_cast<float4*>(&p[tid * 8])     = v0;
    *reinterpret_cast<float4*>(&p[tid * 8 + 4]) = v1;
}

// ---------------- launcher ----------------
extern "C" void kernel_launch(void* const* d_in, const int* in_sizes, int n_in,
                              void* d_out, int out_size) {
    const float* x    = (const float*)d_in[0];
    const float* gn_w = (const float*)d_in[1];
    const float* gn_b = (const float*)d_in[2];
    const float* wq   = (const float*)d_in[3];
    const float* bq   = (const float*)d_in[4];
    const float* wk   = (const float*)d_in[5];
    const float* bk   = (const float*)d_in[6];
    const float* wv   = (const float*)d_in[7];
    const float* bv   = (const float*)d_in[8];
    const float* wp   = (const float*)d_in[9];
    const float* bp   = (const float*)d_in[10];
    float* out = (float*)d_out;

    float *hn, *q, *k, *v, *o, *s;
    cudaGetSymbolAddress((void**)&hn, g_hn);
    cudaGetSymbolAddress((void**)&q,  g_q);
    cudaGetSymbolAddress((void**)&k,  g_k);
    cudaGetSymbolAddress((void**)&v,  g_v);
    cudaGetSymbolAddress((void**)&o,  g_o);
    cudaGetSymbolAddress((void**)&s,  g_s);

    const size_t sCN = (size_t)CDIM * NSP;
    const size_t sNN = (size_t)NSP * NSP;
    const float attn_scale = 0.04419417382415922f;  // 1/sqrt(512)

    gn_kernel<<<BDIM * GROUPS, 512>>>(x, gn_w, gn_b, hn);

    dim3 blk(256);
    dim3 gp(NSP / BN, CDIM / BM, BDIM);   // 32 x 4 x 2
    dim3 gs(NSP / BN, NSP / BM, BDIM);    // 32 x 32 x 2

    // Q/K/V projections: W[512,512] @ hn[512,4096] + b
    gemm_tc<0,0,0><<<gp, blk>>>(wq, hn, q, CDIM, CDIM, NSP, NSP,
                                0, sCN, sCN, bq, 1.f, nullptr);
    gemm_tc<0,0,0><<<gp, blk>>>(wk, hn, k, CDIM, CDIM, NSP, NSP,
                                0, sCN, sCN, bk, 1.f, nullptr);
    gemm_tc<0,0,0><<<gp, blk>>>(wv, hn, v, CDIM, CDIM, NSP, NSP,
                                0, sCN, sCN, bv, 1.f, nullptr);

    // scores[i,j] = (1/sqrt(C)) * sum_c q[c,i] k[c,j]   (TA=1)
    gemm_tc<1,0,1><<<gs, blk>>>(q, k, s, CDIM, NSP, NSP, NSP,
                                sCN, sCN, sNN, nullptr, attn_scale, nullptr);

    softmax_kernel<<<BDIM * NSP, 512>>>(s);

    // o[c,i] = sum_j v[c,j] attn[i,j]   (TB=1)
    gemm_tc<0,1,2><<<gp, blk>>>(v, s, o, NSP, NSP, NSP, NSP,
                                sCN, sNN, sCN, nullptr, 1.f, nullptr);

    // out = x + wp @ o + bp
    gemm_tc<0,0,3><<<gp, blk>>>(wp, o, out, CDIM, CDIM, NSP, NSP,
                                0, sCN, sCN, bp, 1.f, x);
}

// round 4
// speedup vs baseline: 3.2646x; 1.1625x over previous
#include <cuda_runtime.h>
#include <cstdint>
#include <math.h>

#define BDIM 2
#define CDIM 512
#define NSP  4096
#define GROUPS 32
#define CPG  16

// ---- static scratch ----
__device__ float g_hn[(size_t)BDIM * CDIM * NSP];
__device__ float g_q [(size_t)BDIM * CDIM * NSP];
__device__ float g_k [(size_t)BDIM * CDIM * NSP];
__device__ float g_v [(size_t)BDIM * CDIM * NSP];
__device__ float g_o [(size_t)BDIM * CDIM * NSP];
__device__ float g_s [(size_t)BDIM * NSP * NSP];   // 128 MiB scores/attn

// ---------------- reductions ----------------
__device__ __forceinline__ float blockReduceSum(float v, float* sh) {
    #pragma unroll
    for (int o = 16; o; o >>= 1) v += __shfl_down_sync(0xffffffffu, v, o);
    int lane = threadIdx.x & 31, wid = threadIdx.x >> 5;
    if (lane == 0) sh[wid] = v;
    __syncthreads();
    int nw = blockDim.x >> 5;
    v = (threadIdx.x < nw) ? sh[threadIdx.x] : 0.f;
    if (wid == 0) {
        #pragma unroll
        for (int o = 16; o; o >>= 1) v += __shfl_down_sync(0xffffffffu, v, o);
    }
    return v;
}

__device__ __forceinline__ float blockReduceMax(float v, float* sh) {
    #pragma unroll
    for (int o = 16; o; o >>= 1) v = fmaxf(v, __shfl_down_sync(0xffffffffu, v, o));
    int lane = threadIdx.x & 31, wid = threadIdx.x >> 5;
    if (lane == 0) sh[wid] = v;
    __syncthreads();
    int nw = blockDim.x >> 5;
    v = (threadIdx.x < nw) ? sh[threadIdx.x] : -3.0e38f;
    if (wid == 0) {
        #pragma unroll
        for (int o = 16; o; o >>= 1) v = fmaxf(v, __shfl_down_sync(0xffffffffu, v, o));
    }
    return v;
}

// ---------------- GroupNorm ----------------
__global__ void gn_kernel(const float* __restrict__ x,
                          const float* __restrict__ w,
                          const float* __restrict__ bb,
                          float* __restrict__ hn) {
    __shared__ float sh[32];
    __shared__ float s_mean, s_rstd;
    int blk = blockIdx.x;
    int b = blk / GROUPS, g = blk % GROUPS;
    size_t base = ((size_t)b * CDIM + (size_t)g * CPG) * NSP;
    const float* xp = x + base;
    const int TOT = CPG * NSP;

    float s = 0.f, ss = 0.f;
    for (int i = threadIdx.x; i < TOT; i += blockDim.x) {
        float v = xp[i];
        s += v; ss += v * v;
    }
    float tot = blockReduceSum(s, sh);
    __syncthreads();
    float tot2 = blockReduceSum(ss, sh);
    if (threadIdx.x == 0) {
        float mean = tot / (float)TOT;
        float var  = tot2 / (float)TOT - mean * mean;
        s_mean = mean;
        s_rstd = rsqrtf(var + 1e-6f);
    }
    __syncthreads();
    float mean = s_mean, rstd = s_rstd;
    float* hp = hn + base;
    for (int i = threadIdx.x; i < TOT; i += blockDim.x) {
        int c = g * CPG + (i >> 12);
        hp[i] = (xp[i] - mean) * rstd * w[c] + bb[c];
    }
}

// ---------------- tf32 tensor-core GEMM (cp.async pipelined) ----------------
__device__ __forceinline__ void mma_tf32(float* c, const uint32_t* a, const uint32_t* b) {
    asm volatile(
        "mma.sync.aligned.m16n8k8.row.col.f32.tf32.tf32.f32 "
        "{%0,%1,%2,%3}, {%4,%5,%6,%7}, {%8,%9}, {%0,%1,%2,%3};"
        : "+f"(c[0]), "+f"(c[1]), "+f"(c[2]), "+f"(c[3])
        : "r"(a[0]), "r"(a[1]), "r"(a[2]), "r"(a[3]), "r"(b[0]), "r"(b[1]));
}

__device__ __forceinline__ void cpasync16(uint32_t dst, const void* src) {
    asm volatile("cp.async.cg.shared.global [%0], [%1], 16;\n" :: "r"(dst), "l"(src));
}
__device__ __forceinline__ void cpasync_commit() {
    asm volatile("cp.async.commit_group;\n" ::: "memory");
}
__device__ __forceinline__ void cpasync_wait0() {
    asm volatile("cp.async.wait_group 0;\n" ::: "memory");
}

// C[m,n] = sum_k opA(m,k)*opB(k,n); opA = TA? A[k*lda+m] : A[m*lda+k]
//                                   opB = TB? B[n*ldb+k] : B[k*ldb+n]
// EPI: 0 = +bias[m], 1 = *scale, 2 = none, 3 = +bias[m]+resid
#define BM 128
#define BN 128
#define BK 16

template<int TA, int TB, int EPI>
__global__ void __launch_bounds__(256, 2)
gemm_tc(const float* __restrict__ A, const float* __restrict__ B,
        float* __restrict__ C, int K,
        int lda, int ldb, int ldc,
        size_t sA, size_t sB, size_t sC,
        const float* __restrict__ bias, float scale,
        const float* __restrict__ resid) {
    int bz = blockIdx.z;
    A += sA * (size_t)bz;
    B += sB * (size_t)bz;
    C += sC * (size_t)bz;

    const int m0 = blockIdx.y * BM;
    const int n0 = blockIdx.x * BN;

    // smem layouts (conflict-free fragment reads, 16B-aligned cp.async rows):
    //  TA==0: As[m*20 + k]   TA==1: As[k*136 + m]
    //  TB==0: Bs[k*136 + n]  TB==1: Bs[n*20 + k]
    constexpr int ASTR = TA ? (BK * 136) : (BM * 20);
    constexpr int BSTR = TB ? (BN * 20) : (BK * 136);
    __shared__ uint32_t As[2 * ASTR];
    __shared__ uint32_t Bs[2 * BSTR];

    const int t = threadIdx.x;
    const int w = t >> 5, lane = t & 31;
    const int wm = w >> 2, wn = w & 3;        // 2 x 4 warp grid
    const int gr = lane >> 2, gc = lane & 3;  // mma groups

    const uint32_t as_base = (uint32_t)__cvta_generic_to_shared(As);
    const uint32_t bs_base = (uint32_t)__cvta_generic_to_shared(Bs);

    // per-thread fill coordinates (2 float4 each for A and B)
    int a_r[2], a_k[2], b_r[2], b_k[2];
    #pragma unroll
    for (int it = 0; it < 2; it++) {
        int q = t + it * 256;
        if (TA == 0) { a_r[it] = q >> 2;  a_k[it] = (q & 3) << 2; }
        else         { a_r[it] = q >> 5;  a_k[it] = (q & 31) << 2; }  // r=k-row, k=m-col
        if (TB == 0) { b_r[it] = q >> 5;  b_k[it] = (q & 31) << 2; }  // r=k-row, k=n-col
        else         { b_r[it] = q >> 2;  b_k[it] = (q & 3) << 2; }
    }

    auto issue_loads = [&](int kb, int stage) {
        uint32_t ao = as_base + stage * (ASTR * 4);
        uint32_t bo = bs_base + stage * (BSTR * 4);
        #pragma unroll
        for (int it = 0; it < 2; it++) {
            if (TA == 0)
                cpasync16(ao + (a_r[it] * 20 + a_k[it]) * 4,
                          &A[(size_t)(m0 + a_r[it]) * lda + kb + a_k[it]]);
            else
                cpasync16(ao + (a_r[it] * 136 + a_k[it]) * 4,
                          &A[(size_t)(kb + a_r[it]) * lda + m0 + a_k[it]]);
        }
        #pragma unroll
        for (int it = 0; it < 2; it++) {
            if (TB == 0)
                cpasync16(bo + (b_r[it] * 136 + b_k[it]) * 4,
                          &B[(size_t)(kb + b_r[it]) * ldb + n0 + b_k[it]]);
            else
                cpasync16(bo + (b_r[it] * 20 + b_k[it]) * 4,
                          &B[(size_t)(n0 + b_r[it]) * ldb + kb + b_k[it]]);
        }
    };

    float acc[4][4][4];
    #pragma unroll
    for (int i = 0; i < 4; i++)
        #pragma unroll
        for (int j = 0; j < 4; j++)
            #pragma unroll
            for (int r = 0; r < 4; r++) acc[i][j][r] = 0.f;

    issue_loads(0, 0);
    cpasync_commit();

    const int nk = K / BK;
    for (int kb = 0; kb < nk; kb++) {
        cpasync_wait0();
        __syncthreads();

        if (kb + 1 < nk) issue_loads((kb + 1) * BK, (kb + 1) & 1);
        cpasync_commit();

        const uint32_t* Ac = &As[(kb & 1) * ASTR];
        const uint32_t* Bc = &Bs[(kb & 1) * BSTR];

        #pragma unroll
        for (int kk = 0; kk < BK; kk += 8) {
            uint32_t af[4][4];
            #pragma unroll
            for (int mt = 0; mt < 4; mt++) {
                int row = wm * 64 + mt * 16 + gr;
                int k = kk + gc;
                if (TA == 0) {
                    af[mt][0] = Ac[(row)     * 20 + k];
                    af[mt][1] = Ac[(row + 8) * 20 + k];
                    af[mt][2] = Ac[(row)     * 20 + k + 4];
                    af[mt][3] = Ac[(row + 8) * 20 + k + 4];
                } else {
                    af[mt][0] = Ac[(k)     * 136 + row];
                    af[mt][1] = Ac[(k)     * 136 + row + 8];
                    af[mt][2] = Ac[(k + 4) * 136 + row];
                    af[mt][3] = Ac[(k + 4) * 136 + row + 8];
                }
            }
            uint32_t bf[4][2];
            #pragma unroll
            for (int nt = 0; nt < 4; nt++) {
                int col = wn * 32 + nt * 8 + gr;
                int k = kk + gc;
                if (TB == 0) {
                    bf[nt][0] = Bc[(k)     * 136 + col];
                    bf[nt][1] = Bc[(k + 4) * 136 + col];
                } else {
                    bf[nt][0] = Bc[col * 20 + k];
                    bf[nt][1] = Bc[col * 20 + k + 4];
                }
            }
            #pragma unroll
            for (int mt = 0; mt < 4; mt++)
                #pragma unroll
                for (int nt = 0; nt < 4; nt++)
                    mma_tf32(acc[mt][nt], af[mt], bf[nt]);
        }
        __syncthreads();
    }

    // ---- epilogue ----
    #pragma unroll
    for (int mt = 0; mt < 4; mt++) {
        int mA = m0 + wm * 64 + mt * 16 + gr;
        int mB = mA + 8;
        float biasA = (EPI == 0 || EPI == 3) ? bias[mA] : 0.f;
        float biasB = (EPI == 0 || EPI == 3) ? bias[mB] : 0.f;
        #pragma unroll
        for (int nt = 0; nt < 4; nt++) {
            int n = n0 + wn * 32 + nt * 8 + 2 * gc;
            float v0 = acc[mt][nt][0], v1 = acc[mt][nt][1];
            float v2 = acc[mt][nt][2], v3 = acc[mt][nt][3];
            if (EPI == 1) { v0 *= scale; v1 *= scale; v2 *= scale; v3 *= scale; }
            v0 += biasA; v1 += biasA; v2 += biasB; v3 += biasB;
            if (EPI == 3) {
                const float* rp = resid + sC * (size_t)bz;
                float2 r0 = *reinterpret_cast<const float2*>(&rp[(size_t)mA * ldc + n]);
                float2 r1 = *reinterpret_cast<const float2*>(&rp[(size_t)mB * ldc + n]);
                v0 += r0.x; v1 += r0.y; v2 += r1.x; v3 += r1.y;
            }
            *reinterpret_cast<float2*>(&C[(size_t)mA * ldc + n]) = make_float2(v0, v1);
            *reinterpret_cast<float2*>(&C[(size_t)mB * ldc + n]) = make_float2(v2, v3);
        }
    }
}

// ---------------- register-resident row softmax ----------------
__global__ void __launch_bounds__(512)
softmax_kernel(float* __restrict__ s) {
    __shared__ float sh[32];
    __shared__ float s_bc;
    size_t row = blockIdx.x;
    float* p = s + row * (size_t)NSP;
    int tid = threadIdx.x;

    float4 v0 = *reinterpret_cast<const float4*>(&p[tid * 8]);
    float4 v1 = *reinterpret_cast<const float4*>(&p[tid * 8 + 4]);

    float m = fmaxf(fmaxf(fmaxf(v0.x, v0.y), fmaxf(v0.z, v0.w)),
                    fmaxf(fmaxf(v1.x, v1.y), fmaxf(v1.z, v1.w)));
    m = blockReduceMax(m, sh);
    if (tid == 0) s_bc = m;
    __syncthreads();
    m = s_bc;
    __syncthreads();

    v0.x = __expf(v0.x - m); v0.y = __expf(v0.y - m);
    v0.z = __expf(v0.z - m); v0.w = __expf(v0.w - m);
    v1.x = __expf(v1.x - m); v1.y = __expf(v1.y - m);
    v1.z = __expf(v1.z - m); v1.w = __expf(v1.w - m);
    float sum = v0.x + v0.y + v0.z + v0.w + v1.x + v1.y + v1.z + v1.w;
    sum = blockReduceSum(sum, sh);
    if (tid == 0) s_bc = 1.f / sum;
    __syncthreads();
    float inv = s_bc;

    v0.x *= inv; v0.y *= inv; v0.z *= inv; v0.w *= inv;
    v1.x *= inv; v1.y *= inv; v1.z *= inv; v1.w *= inv;
    *reinterpret_cast<float4*>(&p[tid * 8])     = v0;
    *reinterpret_cast<float4*>(&p[tid * 8 + 4]) = v1;
}

// ---------------- launcher ----------------
extern "C" void kernel_launch(void* const* d_in, const int* in_sizes, int n_in,
                              void* d_out, int out_size) {
    const float* x    = (const float*)d_in[0];
    const float* gn_w = (const float*)d_in[1];
    const float* gn_b = (const float*)d_in[2];
    const float* wq   = (const float*)d_in[3];
    const float* bq   = (const float*)d_in[4];
    const float* wk   = (const float*)d_in[5];
    const float* bk   = (const float*)d_in[6];
    const float* wv   = (const float*)d_in[7];
    const float* bv   = (const float*)d_in[8];
    const float* wp   = (const float*)d_in[9];
    const float* bp   = (const float*)d_in[10];
    float* out = (float*)d_out;

    float *hn, *q, *k, *v, *o, *s;
    cudaGetSymbolAddress((void**)&hn, g_hn);
    cudaGetSymbolAddress((void**)&q,  g_q);
    cudaGetSymbolAddress((void**)&k,  g_k);
    cudaGetSymbolAddress((void**)&v,  g_v);
    cudaGetSymbolAddress((void**)&o,  g_o);
    cudaGetSymbolAddress((void**)&s,  g_s);

    const size_t sCN = (size_t)CDIM * NSP;
    const size_t sNN = (size_t)NSP * NSP;
    const float attn_scale = 0.04419417382415922f;  // 1/sqrt(512)

    gn_kernel<<<BDIM * GROUPS, 512>>>(x, gn_w, gn_b, hn);

    dim3 blk(256);
    dim3 gp(NSP / BN, CDIM / BM, BDIM);   // 32 x 4 x 2
    dim3 gs(NSP / BN, NSP / BM, BDIM);    // 32 x 32 x 2

    // Q/K/V projections: W[512,512] @ hn[512,4096] + b
    gemm_tc<0,0,0><<<gp, blk>>>(wq, hn, q, CDIM, CDIM, NSP, NSP,
                                0, sCN, sCN, bq, 1.f, nullptr);
    gemm_tc<0,0,0><<<gp, blk>>>(wk, hn, k, CDIM, CDIM, NSP, NSP,
                                0, sCN, sCN, bk, 1.f, nullptr);
    gemm_tc<0,0,0><<<gp, blk>>>(wv, hn, v, CDIM, CDIM, NSP, NSP,
                                0, sCN, sCN, bv, 1.f, nullptr);

    // scores[i,j] = (1/sqrt(C)) * sum_c q[c,i] k[c,j]   (TA=1)
    gemm_tc<1,0,1><<<gs, blk>>>(q, k, s, CDIM, NSP, NSP, NSP,
                                sCN, sCN, sNN, nullptr, attn_scale, nullptr);

    softmax_kernel<<<BDIM * NSP, 512>>>(s);

    // o[c,i] = sum_j v[c,j] attn[i,j]   (TB=1)
    gemm_tc<0,1,2><<<gp, blk>>>(v, s, o, NSP, NSP, NSP, NSP,
                                sCN, sNN, sCN, nullptr, 1.f, nullptr);

    // out = x + wp @ o + bp
    gemm_tc<0,0,3><<<gp, blk>>>(wp, o, out, CDIM, CDIM, NSP, NSP,
                                0, sCN, sCN, bp, 1.f, x);
}

// round 6
// speedup vs baseline: 3.4742x; 1.0642x over previous
#include <cuda_runtime.h>
#include <cstdint>
#include <math.h>

#define BDIM 2
#define CDIM 512
#define NSP  4096
#define GROUPS 32
#define CPG  16

// ---- static scratch ----
__device__ float g_hn[(size_t)BDIM * CDIM * NSP];
__device__ float g_q [(size_t)BDIM * CDIM * NSP];
__device__ float g_k [(size_t)BDIM * CDIM * NSP];
__device__ float g_v [(size_t)BDIM * CDIM * NSP];
__device__ float g_o [(size_t)BDIM * CDIM * NSP];
__device__ float g_s [(size_t)BDIM * NSP * NSP];   // 128 MiB exp-scores
__device__ float g_rs[(size_t)BDIM * NSP];         // 1/rowsum

// ---------------- reductions ----------------
__device__ __forceinline__ float blockReduceSum(float v, float* sh) {
    #pragma unroll
    for (int o = 16; o; o >>= 1) v += __shfl_down_sync(0xffffffffu, v, o);
    int lane = threadIdx.x & 31, wid = threadIdx.x >> 5;
    if (lane == 0) sh[wid] = v;
    __syncthreads();
    int nw = blockDim.x >> 5;
    v = (threadIdx.x < nw) ? sh[threadIdx.x] : 0.f;
    if (wid == 0) {
        #pragma unroll
        for (int o = 16; o; o >>= 1) v += __shfl_down_sync(0xffffffffu, v, o);
    }
    return v;
}

// ---------------- GroupNorm ----------------
__global__ void gn_kernel(const float* __restrict__ x,
                          const float* __restrict__ w,
                          const float* __restrict__ bb,
                          float* __restrict__ hn) {
    __shared__ float sh[32];
    __shared__ float s_mean, s_rstd;
    int blk = blockIdx.x;
    int b = blk / GROUPS, g = blk % GROUPS;
    size_t base = ((size_t)b * CDIM + (size_t)g * CPG) * NSP;
    const float* xp = x + base;
    const int TOT = CPG * NSP;

    float s = 0.f, ss = 0.f;
    for (int i = threadIdx.x; i < TOT; i += blockDim.x) {
        float v = xp[i];
        s += v; ss += v * v;
    }
    float tot = blockReduceSum(s, sh);
    __syncthreads();
    float tot2 = blockReduceSum(ss, sh);
    if (threadIdx.x == 0) {
        float mean = tot / (float)TOT;
        float var  = tot2 / (float)TOT - mean * mean;
        s_mean = mean;
        s_rstd = rsqrtf(var + 1e-6f);
    }
    __syncthreads();
    float mean = s_mean, rstd = s_rstd;
    float* hp = hn + base;
    for (int i = threadIdx.x; i < TOT; i += blockDim.x) {
        int c = g * CPG + (i >> 12);
        hp[i] = (xp[i] - mean) * rstd * w[c] + bb[c];
    }
}

// ---------------- tf32 tensor-core GEMM (3-stage cp.async) ----------------
__device__ __forceinline__ void mma_tf32(float* c, const uint32_t* a, const uint32_t* b) {
    asm volatile(
        "mma.sync.aligned.m16n8k8.row.col.f32.tf32.tf32.f32 "
        "{%0,%1,%2,%3}, {%4,%5,%6,%7}, {%8,%9}, {%0,%1,%2,%3};"
        : "+f"(c[0]), "+f"(c[1]), "+f"(c[2]), "+f"(c[3])
        : "r"(a[0]), "r"(a[1]), "r"(a[2]), "r"(a[3]), "r"(b[0]), "r"(b[1]));
}

__device__ __forceinline__ void cpasync16(uint32_t dst, const void* src) {
    asm volatile("cp.async.cg.shared.global [%0], [%1], 16;\n" :: "r"(dst), "l"(src));
}
__device__ __forceinline__ void cpasync_commit() {
    asm volatile("cp.async.commit_group;\n" ::: "memory");
}
__device__ __forceinline__ void cpasync_wait1() {
    asm volatile("cp.async.wait_group 1;\n" ::: "memory");
}

// C[m,n] = sum_k opA(m,k)*opB(k,n); opA = TA? A[k*lda+m] : A[m*lda+k]
//                                   opB = TB? B[n*ldb+k] : B[k*ldb+n]
// EPI: 0 = +bias[m], 1 = exp(v*scale), 2 = none, 3 = +bias[m]+resid,
//      4 = v * colscale[bz*NSP + n]
#define BM 128
#define BN 128
#define BK 16
#define NSTAGE 3

template<int TA, int TB, int EPI>
__global__ void __launch_bounds__(256, 2)
gemm_tc(const float* __restrict__ A, const float* __restrict__ B,
        float* __restrict__ C, int K,
        int lda, int ldb, int ldc,
        size_t sA, size_t sB, size_t sC,
        const float* __restrict__ bias, float scale,
        const float* __restrict__ resid, const float* __restrict__ colscale) {
    int bz = blockIdx.z;
    A += sA * (size_t)bz;
    B += sB * (size_t)bz;
    C += sC * (size_t)bz;
    if (EPI == 4) colscale += (size_t)bz * NSP;   // per-batch rowsum base

    const int m0 = blockIdx.y * BM;
    const int n0 = blockIdx.x * BN;

    constexpr int ASTR = TA ? (BK * 136) : (BM * 20);
    constexpr int BSTR = TB ? (BN * 20) : (BK * 136);
    extern __shared__ uint32_t dsm[];
    uint32_t* As = dsm;
    uint32_t* Bs = dsm + NSTAGE * ASTR;

    const int t = threadIdx.x;
    const int w = t >> 5, lane = t & 31;
    const int wm = w >> 2, wn = w & 3;        // 2 x 4 warp grid
    const int gr = lane >> 2, gc = lane & 3;

    const uint32_t as_base = (uint32_t)__cvta_generic_to_shared(As);
    const uint32_t bs_base = (uint32_t)__cvta_generic_to_shared(Bs);

    int a_r[2], a_k[2], b_r[2], b_k[2];
    #pragma unroll
    for (int it = 0; it < 2; it++) {
        int q = t + it * 256;
        if (TA == 0) { a_r[it] = q >> 2;  a_k[it] = (q & 3) << 2; }
        else         { a_r[it] = q >> 5;  a_k[it] = (q & 31) << 2; }
        if (TB == 0) { b_r[it] = q >> 5;  b_k[it] = (q & 31) << 2; }
        else         { b_r[it] = q >> 2;  b_k[it] = (q & 3) << 2; }
    }

    auto issue_loads = [&](int kb, int stage) {
        uint32_t ao = as_base + stage * (ASTR * 4);
        uint32_t bo = bs_base + stage * (BSTR * 4);
        #pragma unroll
        for (int it = 0; it < 2; it++) {
            if (TA == 0)
                cpasync16(ao + (a_r[it] * 20 + a_k[it]) * 4,
                          &A[(size_t)(m0 + a_r[it]) * lda + kb + a_k[it]]);
            else
                cpasync16(ao + (a_r[it] * 136 + a_k[it]) * 4,
                          &A[(size_t)(kb + a_r[it]) * lda + m0 + a_k[it]]);
        }
        #pragma unroll
        for (int it = 0; it < 2; it++) {
            if (TB == 0)
                cpasync16(bo + (b_r[it] * 136 + b_k[it]) * 4,
                          &B[(size_t)(kb + b_r[it]) * ldb + n0 + b_k[it]]);
            else
                cpasync16(bo + (b_r[it] * 20 + b_k[it]) * 4,
                          &B[(size_t)(n0 + b_r[it]) * ldb + kb + b_k[it]]);
        }
    };

    float acc[4][4][4];
    #pragma unroll
    for (int i = 0; i < 4; i++)
        #pragma unroll
        for (int j = 0; j < 4; j++)
            #pragma unroll
            for (int r = 0; r < 4; r++) acc[i][j][r] = 0.f;

    const int nk = K / BK;
    issue_loads(0, 0);
    cpasync_commit();
    issue_loads(BK, 1);
    cpasync_commit();

    int st_cur = 0;       // stage of current compute
    int st_nxt = 2;       // stage for prefetch (kb+2)
    for (int kb = 0; kb < nk; kb++) {
        cpasync_wait1();      // group kb complete (kb+1 may be in flight)
        __syncthreads();      // visibility + skew bound

        if (kb + 2 < nk) issue_loads((kb + 2) * BK, st_nxt);
        cpasync_commit();

        const uint32_t* Ac = &As[st_cur * ASTR];
        const uint32_t* Bc = &Bs[st_cur * BSTR];

        #pragma unroll
        for (int kk = 0; kk < BK; kk += 8) {
            uint32_t af[4][4];
            #pragma unroll
            for (int mt = 0; mt < 4; mt++) {
                int row = wm * 64 + mt * 16 + gr;
                int k = kk + gc;
                if (TA == 0) {
                    af[mt][0] = Ac[(row)     * 20 + k];
                    af[mt][1] = Ac[(row + 8) * 20 + k];
                    af[mt][2] = Ac[(row)     * 20 + k + 4];
                    af[mt][3] = Ac[(row + 8) * 20 + k + 4];
                } else {
                    af[mt][0] = Ac[(k)     * 136 + row];
                    af[mt][1] = Ac[(k)     * 136 + row + 8];
                    af[mt][2] = Ac[(k + 4) * 136 + row];
                    af[mt][3] = Ac[(k + 4) * 136 + row + 8];
                }
            }
            uint32_t bf[4][2];
            #pragma unroll
            for (int nt = 0; nt < 4; nt++) {
                int col = wn * 32 + nt * 8 + gr;
                int k = kk + gc;
                if (TB == 0) {
                    bf[nt][0] = Bc[(k)     * 136 + col];
                    bf[nt][1] = Bc[(k + 4) * 136 + col];
                } else {
                    bf[nt][0] = Bc[col * 20 + k];
                    bf[nt][1] = Bc[col * 20 + k + 4];
                }
            }
            #pragma unroll
            for (int mt = 0; mt < 4; mt++)
                #pragma unroll
                for (int nt = 0; nt < 4; nt++)
                    mma_tf32(acc[mt][nt], af[mt], bf[nt]);
        }
        st_cur = (st_cur == NSTAGE - 1) ? 0 : st_cur + 1;
        st_nxt = (st_nxt == NSTAGE - 1) ? 0 : st_nxt + 1;
    }

    // ---- epilogue ----
    #pragma unroll
    for (int mt = 0; mt < 4; mt++) {
        int mA = m0 + wm * 64 + mt * 16 + gr;
        int mB = mA + 8;
        float biasA = (EPI == 0 || EPI == 3) ? bias[mA] : 0.f;
        float biasB = (EPI == 0 || EPI == 3) ? bias[mB] : 0.f;
        #pragma unroll
        for (int nt = 0; nt < 4; nt++) {
            int n = n0 + wn * 32 + nt * 8 + 2 * gc;
            float v0 = acc[mt][nt][0], v1 = acc[mt][nt][1];
            float v2 = acc[mt][nt][2], v3 = acc[mt][nt][3];
            if (EPI == 1) {
                v0 = __expf(v0 * scale); v1 = __expf(v1 * scale);
                v2 = __expf(v2 * scale); v3 = __expf(v3 * scale);
            }
            if (EPI == 4) {
                float c0 = colscale[n], c1 = colscale[n + 1];
                v0 *= c0; v1 *= c1; v2 *= c0; v3 *= c1;
            }
            v0 += biasA; v1 += biasA; v2 += biasB; v3 += biasB;
            if (EPI == 3) {
                const float* rp = resid + sC * (size_t)bz;
                float2 r0 = *reinterpret_cast<const float2*>(&rp[(size_t)mA * ldc + n]);
                float2 r1 = *reinterpret_cast<const float2*>(&rp[(size_t)mB * ldc + n]);
                v0 += r0.x; v1 += r0.y; v2 += r1.x; v3 += r1.y;
            }
            *reinterpret_cast<float2*>(&C[(size_t)mA * ldc + n]) = make_float2(v0, v1);
            *reinterpret_cast<float2*>(&C[(size_t)mB * ldc + n]) = make_float2(v2, v3);
        }
    }
}

// ---------------- row-sum reciprocal ----------------
__global__ void __launch_bounds__(256)
rowsum_kernel(const float* __restrict__ s, float* __restrict__ inv) {
    __shared__ float sh[32];
    size_t row = blockIdx.x;
    const float* p = s + row * (size_t)NSP;
    int tid = threadIdx.x;
    float sum = 0.f;
    #pragma unroll
    for (int it = 0; it < 4; it++) {
        float4 v = *reinterpret_cast<const float4*>(&p[(tid + it * 256) * 4]);
        sum += v.x + v.y + v.z + v.w;
    }
    sum = blockReduceSum(sum, sh);
    if (tid == 0) inv[row] = 1.f / sum;
}

// ---------------- launcher ----------------
extern "C" void kernel_launch(void* const* d_in, const int* in_sizes, int n_in,
                              void* d_out, int out_size) {
    const float* x    = (const float*)d_in[0];
    const float* gn_w = (const float*)d_in[1];
    const float* gn_b = (const float*)d_in[2];
    const float* wq   = (const float*)d_in[3];
    const float* bq   = (const float*)d_in[4];
    const float* wk   = (const float*)d_in[5];
    const float* bk   = (const float*)d_in[6];
    const float* wv   = (const float*)d_in[7];
    const float* bv   = (const float*)d_in[8];
    const float* wp   = (const float*)d_in[9];
    const float* bp   = (const float*)d_in[10];
    float* out = (float*)d_out;

    float *hn, *q, *k, *v, *o, *s, *rs;
    cudaGetSymbolAddress((void**)&hn, g_hn);
    cudaGetSymbolAddress((void**)&q,  g_q);
    cudaGetSymbolAddress((void**)&k,  g_k);
    cudaGetSymbolAddress((void**)&v,  g_v);
    cudaGetSymbolAddress((void**)&o,  g_o);
    cudaGetSymbolAddress((void**)&s,  g_s);
    cudaGetSymbolAddress((void**)&rs, g_rs);

    const size_t sCN = (size_t)CDIM * NSP;
    const size_t sNN = (size_t)NSP * NSP;
    const float attn_scale = 0.04419417382415922f;  // 1/sqrt(512)

    const int smem00 = NSTAGE * (BM * 20 + BK * 136) * 4;  // 56832
    const int smem10 = NSTAGE * (BK * 136 + BK * 136) * 4; // 52224
    const int smem01 = NSTAGE * (BM * 20 + BN * 20) * 4;   // 61440
    cudaFuncSetAttribute(gemm_tc<0,0,0>, cudaFuncAttributeMaxDynamicSharedMemorySize, smem00);
    cudaFuncSetAttribute(gemm_tc<1,0,1>, cudaFuncAttributeMaxDynamicSharedMemorySize, smem10);
    cudaFuncSetAttribute(gemm_tc<0,1,4>, cudaFuncAttributeMaxDynamicSharedMemorySize, smem01);
    cudaFuncSetAttribute(gemm_tc<0,0,3>, cudaFuncAttributeMaxDynamicSharedMemorySize, smem00);

    gn_kernel<<<BDIM * GROUPS, 512>>>(x, gn_w, gn_b, hn);

    dim3 blk(256);
    dim3 gp(NSP / BN, CDIM / BM, BDIM);   // 32 x 4 x 2
    dim3 gs(NSP / BN, NSP / BM, BDIM);    // 32 x 32 x 2

    // Q/K/V projections
    gemm_tc<0,0,0><<<gp, blk, smem00>>>(wq, hn, q, CDIM, CDIM, NSP, NSP,
                                        0, sCN, sCN, bq, 1.f, nullptr, nullptr);
    gemm_tc<0,0,0><<<gp, blk, smem00>>>(wk, hn, k, CDIM, CDIM, NSP, NSP,
                                        0, sCN, sCN, bk, 1.f, nullptr, nullptr);
    gemm_tc<0,0,0><<<gp, blk, smem00>>>(wv, hn, v, CDIM, CDIM, NSP, NSP,
                                        0, sCN, sCN, bv, 1.f, nullptr, nullptr);

    // e[i,j] = exp(q.k / sqrt(C))   (fused exp epilogue)
    gemm_tc<1,0,1><<<gs, blk, smem10>>>(q, k, s, CDIM, NSP, NSP, NSP,
                                        sCN, sCN, sNN, nullptr, attn_scale,
                                        nullptr, nullptr);

    rowsum_kernel<<<BDIM * NSP, 256>>>(s, rs);

    // o[c,i] = (sum_j v[c,j] e[i,j]) * inv_rowsum[i]
    gemm_tc<0,1,4><<<gp, blk, smem01>>>(v, s, o, NSP, NSP, NSP, NSP,
                                        sCN, sNN, sCN, nullptr, 1.f,
                                        nullptr, rs);

    // out = x + wp @ o + bp
    gemm_tc<0,0,3><<<gp, blk, smem00>>>(wp, o, out, CDIM, CDIM, NSP, NSP,
                                        0, sCN, sCN, bp, 1.f, x, nullptr);
}

// round 7
// speedup vs baseline: 3.4844x; 1.0029x over previous
#include <cuda_runtime.h>
#include <cstdint>
#include <math.h>

#define BDIM 2
#define CDIM 512
#define NSP  4096
#define GROUPS 32
#define CPG  16

// ---- static scratch ----
__device__ float g_hn[(size_t)BDIM * CDIM * NSP];
__device__ float g_q [(size_t)BDIM * CDIM * NSP];
__device__ float g_k [(size_t)BDIM * CDIM * NSP];
__device__ float g_v [(size_t)BDIM * CDIM * NSP];
__device__ float g_o [(size_t)BDIM * CDIM * NSP];
__device__ float g_s [(size_t)BDIM * NSP * NSP];   // 128 MiB exp-scores
__device__ float g_rs[(size_t)BDIM * NSP];         // 1/rowsum

// ---------------- reductions ----------------
__device__ __forceinline__ float blockReduceSum(float v, float* sh) {
    #pragma unroll
    for (int o = 16; o; o >>= 1) v += __shfl_down_sync(0xffffffffu, v, o);
    int lane = threadIdx.x & 31, wid = threadIdx.x >> 5;
    if (lane == 0) sh[wid] = v;
    __syncthreads();
    int nw = blockDim.x >> 5;
    v = (threadIdx.x < nw) ? sh[threadIdx.x] : 0.f;
    if (wid == 0) {
        #pragma unroll
        for (int o = 16; o; o >>= 1) v += __shfl_down_sync(0xffffffffu, v, o);
    }
    return v;
}

// ---------------- GroupNorm ----------------
__global__ void gn_kernel(const float* __restrict__ x,
                          const float* __restrict__ w,
                          const float* __restrict__ bb,
                          float* __restrict__ hn) {
    __shared__ float sh[32];
    __shared__ float s_mean, s_rstd;
    int blk = blockIdx.x;
    int b = blk / GROUPS, g = blk % GROUPS;
    size_t base = ((size_t)b * CDIM + (size_t)g * CPG) * NSP;
    const float* xp = x + base;
    const int TOT = CPG * NSP;

    float s = 0.f, ss = 0.f;
    for (int i = threadIdx.x; i < TOT; i += blockDim.x) {
        float v = xp[i];
        s += v; ss += v * v;
    }
    float tot = blockReduceSum(s, sh);
    __syncthreads();
    float tot2 = blockReduceSum(ss, sh);
    if (threadIdx.x == 0) {
        float mean = tot / (float)TOT;
        float var  = tot2 / (float)TOT - mean * mean;
        s_mean = mean;
        s_rstd = rsqrtf(var + 1e-6f);
    }
    __syncthreads();
    float mean = s_mean, rstd = s_rstd;
    float* hp = hn + base;
    for (int i = threadIdx.x; i < TOT; i += blockDim.x) {
        int c = g * CPG + (i >> 12);
        hp[i] = (xp[i] - mean) * rstd * w[c] + bb[c];
    }
}

// ---------------- tf32 tensor-core GEMM (3-stage cp.async) ----------------
__device__ __forceinline__ void mma_tf32(float* c, const uint32_t* a, const uint32_t* b) {
    asm volatile(
        "mma.sync.aligned.m16n8k8.row.col.f32.tf32.tf32.f32 "
        "{%0,%1,%2,%3}, {%4,%5,%6,%7}, {%8,%9}, {%0,%1,%2,%3};"
        : "+f"(c[0]), "+f"(c[1]), "+f"(c[2]), "+f"(c[3])
        : "r"(a[0]), "r"(a[1]), "r"(a[2]), "r"(a[3]), "r"(b[0]), "r"(b[1]));
}

__device__ __forceinline__ void cpasync16(uint32_t dst, const void* src) {
    asm volatile("cp.async.cg.shared.global [%0], [%1], 16;\n" :: "r"(dst), "l"(src));
}
__device__ __forceinline__ void cpasync_commit() {
    asm volatile("cp.async.commit_group;\n" ::: "memory");
}
__device__ __forceinline__ void cpasync_wait1() {
    asm volatile("cp.async.wait_group 1;\n" ::: "memory");
}

// C[m,n] = sum_k opA(m,k)*opB(k,n); opA = TA? A[k*lda+m] : A[m*lda+k]
//                                   opB = TB? B[n*ldb+k] : B[k*ldb+n]
// EPI: 0 = +bias[m], 1 = exp(v*scale), 2 = none, 3 = +bias[m]+resid,
//      4 = v * colscale[bz*NSP + n]
#define BM 128
#define BN 128
#define BK 16
#define NSTAGE 3

template<int TA, int TB, int EPI>
__global__ void __launch_bounds__(256, 2)
gemm_tc(const float* __restrict__ A, const float* __restrict__ B,
        float* __restrict__ C, int K,
        int lda, int ldb, int ldc,
        size_t sA, size_t sB, size_t sC,
        const float* __restrict__ bias, float scale,
        const float* __restrict__ resid, const float* __restrict__ colscale) {
    int bz = blockIdx.z;
    A += sA * (size_t)bz;
    B += sB * (size_t)bz;
    C += sC * (size_t)bz;
    if (EPI == 4) colscale += (size_t)bz * NSP;   // per-batch rowsum base

    const int m0 = blockIdx.y * BM;
    const int n0 = blockIdx.x * BN;

    constexpr int ASTR = TA ? (BK * 136) : (BM * 20);
    constexpr int BSTR = TB ? (BN * 20) : (BK * 136);
    extern __shared__ uint32_t dsm[];
    uint32_t* As = dsm;
    uint32_t* Bs = dsm + NSTAGE * ASTR;

    const int t = threadIdx.x;
    const int w = t >> 5, lane = t & 31;
    const int wm = w >> 2, wn = w & 3;        // 2 x 4 warp grid
    const int gr = lane >> 2, gc = lane & 3;

    const uint32_t as_base = (uint32_t)__cvta_generic_to_shared(As);
    const uint32_t bs_base = (uint32_t)__cvta_generic_to_shared(Bs);

    int a_r[2], a_k[2], b_r[2], b_k[2];
    #pragma unroll
    for (int it = 0; it < 2; it++) {
        int q = t + it * 256;
        if (TA == 0) { a_r[it] = q >> 2;  a_k[it] = (q & 3) << 2; }
        else         { a_r[it] = q >> 5;  a_k[it] = (q & 31) << 2; }
        if (TB == 0) { b_r[it] = q >> 5;  b_k[it] = (q & 31) << 2; }
        else         { b_r[it] = q >> 2;  b_k[it] = (q & 3) << 2; }
    }

    auto issue_loads = [&](int kb, int stage) {
        uint32_t ao = as_base + stage * (ASTR * 4);
        uint32_t bo = bs_base + stage * (BSTR * 4);
        #pragma unroll
        for (int it = 0; it < 2; it++) {
            if (TA == 0)
                cpasync16(ao + (a_r[it] * 20 + a_k[it]) * 4,
                          &A[(size_t)(m0 + a_r[it]) * lda + kb + a_k[it]]);
            else
                cpasync16(ao + (a_r[it] * 136 + a_k[it]) * 4,
                          &A[(size_t)(kb + a_r[it]) * lda + m0 + a_k[it]]);
        }
        #pragma unroll
        for (int it = 0; it < 2; it++) {
            if (TB == 0)
                cpasync16(bo + (b_r[it] * 136 + b_k[it]) * 4,
                          &B[(size_t)(kb + b_r[it]) * ldb + n0 + b_k[it]]);
            else
                cpasync16(bo + (b_r[it] * 20 + b_k[it]) * 4,
                          &B[(size_t)(n0 + b_r[it]) * ldb + kb + b_k[it]]);
        }
    };

    float acc[4][4][4];
    #pragma unroll
    for (int i = 0; i < 4; i++)
        #pragma unroll
        for (int j = 0; j < 4; j++)
            #pragma unroll
            for (int r = 0; r < 4; r++) acc[i][j][r] = 0.f;

    const int nk = K / BK;
    issue_loads(0, 0);
    cpasync_commit();
    issue_loads(BK, 1);
    cpasync_commit();

    int st_cur = 0;       // stage of current compute
    int st_nxt = 2;       // stage for prefetch (kb+2)
    for (int kb = 0; kb < nk; kb++) {
        cpasync_wait1();      // group kb complete (kb+1 may be in flight)
        __syncthreads();      // visibility + skew bound

        if (kb + 2 < nk) issue_loads((kb + 2) * BK, st_nxt);
        cpasync_commit();

        const uint32_t* Ac = &As[st_cur * ASTR];
        const uint32_t* Bc = &Bs[st_cur * BSTR];

        #pragma unroll
        for (int kk = 0; kk < BK; kk += 8) {
            uint32_t af[4][4];
            #pragma unroll
            for (int mt = 0; mt < 4; mt++) {
                int row = wm * 64 + mt * 16 + gr;
                int k = kk + gc;
                if (TA == 0) {
                    af[mt][0] = Ac[(row)     * 20 + k];
                    af[mt][1] = Ac[(row + 8) * 20 + k];
                    af[mt][2] = Ac[(row)     * 20 + k + 4];
                    af[mt][3] = Ac[(row + 8) * 20 + k + 4];
                } else {
                    af[mt][0] = Ac[(k)     * 136 + row];
                    af[mt][1] = Ac[(k)     * 136 + row + 8];
                    af[mt][2] = Ac[(k + 4) * 136 + row];
                    af[mt][3] = Ac[(k + 4) * 136 + row + 8];
                }
            }
            uint32_t bf[4][2];
            #pragma unroll
            for (int nt = 0; nt < 4; nt++) {
                int col = wn * 32 + nt * 8 + gr;
                int k = kk + gc;
                if (TB == 0) {
                    bf[nt][0] = Bc[(k)     * 136 + col];
                    bf[nt][1] = Bc[(k + 4) * 136 + col];
                } else {
                    bf[nt][0] = Bc[col * 20 + k];
                    bf[nt][1] = Bc[col * 20 + k + 4];
                }
            }
            #pragma unroll
            for (int mt = 0; mt < 4; mt++)
                #pragma unroll
                for (int nt = 0; nt < 4; nt++)
                    mma_tf32(acc[mt][nt], af[mt], bf[nt]);
        }
        st_cur = (st_cur == NSTAGE - 1) ? 0 : st_cur + 1;
        st_nxt = (st_nxt == NSTAGE - 1) ? 0 : st_nxt + 1;
    }

    // ---- epilogue ----
    #pragma unroll
    for (int mt = 0; mt < 4; mt++) {
        int mA = m0 + wm * 64 + mt * 16 + gr;
        int mB = mA + 8;
        float biasA = (EPI == 0 || EPI == 3) ? bias[mA] : 0.f;
        float biasB = (EPI == 0 || EPI == 3) ? bias[mB] : 0.f;
        #pragma unroll
        for (int nt = 0; nt < 4; nt++) {
            int n = n0 + wn * 32 + nt * 8 + 2 * gc;
            float v0 = acc[mt][nt][0], v1 = acc[mt][nt][1];
            float v2 = acc[mt][nt][2], v3 = acc[mt][nt][3];
            if (EPI == 1) {
                v0 = __expf(v0 * scale); v1 = __expf(v1 * scale);
                v2 = __expf(v2 * scale); v3 = __expf(v3 * scale);
            }
            if (EPI == 4) {
                float c0 = colscale[n], c1 = colscale[n + 1];
                v0 *= c0; v1 *= c1; v2 *= c0; v3 *= c1;
            }
            v0 += biasA; v1 += biasA; v2 += biasB; v3 += biasB;
            if (EPI == 3) {
                const float* rp = resid + sC * (size_t)bz;
                float2 r0 = *reinterpret_cast<const float2*>(&rp[(size_t)mA * ldc + n]);
                float2 r1 = *reinterpret_cast<const float2*>(&rp[(size_t)mB * ldc + n]);
                v0 += r0.x; v1 += r0.y; v2 += r1.x; v3 += r1.y;
            }
            *reinterpret_cast<float2*>(&C[(size_t)mA * ldc + n]) = make_float2(v0, v1);
            *reinterpret_cast<float2*>(&C[(size_t)mB * ldc + n]) = make_float2(v2, v3);
        }
    }
}

// ---------------- row-sum reciprocal ----------------
__global__ void __launch_bounds__(256)
rowsum_kernel(const float* __restrict__ s, float* __restrict__ inv) {
    __shared__ float sh[32];
    size_t row = blockIdx.x;
    const float* p = s + row * (size_t)NSP;
    int tid = threadIdx.x;
    float sum = 0.f;
    #pragma unroll
    for (int it = 0; it < 4; it++) {
        float4 v = *reinterpret_cast<const float4*>(&p[(tid + it * 256) * 4]);
        sum += v.x + v.y + v.z + v.w;
    }
    sum = blockReduceSum(sum, sh);
    if (tid == 0) inv[row] = 1.f / sum;
}

// ---------------- launcher ----------------
extern "C" void kernel_launch(void* const* d_in, const int* in_sizes, int n_in,
                              void* d_out, int out_size) {
    const float* x    = (const float*)d_in[0];
    const float* gn_w = (const float*)d_in[1];
    const float* gn_b = (const float*)d_in[2];
    const float* wq   = (const float*)d_in[3];
    const float* bq   = (const float*)d_in[4];
    const float* wk   = (const float*)d_in[5];
    const float* bk   = (const float*)d_in[6];
    const float* wv   = (const float*)d_in[7];
    const float* bv   = (const float*)d_in[8];
    const float* wp   = (const float*)d_in[9];
    const float* bp   = (const float*)d_in[10];
    float* out = (float*)d_out;

    float *hn, *q, *k, *v, *o, *s, *rs;
    cudaGetSymbolAddress((void**)&hn, g_hn);
    cudaGetSymbolAddress((void**)&q,  g_q);
    cudaGetSymbolAddress((void**)&k,  g_k);
    cudaGetSymbolAddress((void**)&v,  g_v);
    cudaGetSymbolAddress((void**)&o,  g_o);
    cudaGetSymbolAddress((void**)&s,  g_s);
    cudaGetSymbolAddress((void**)&rs, g_rs);

    const size_t sCN = (size_t)CDIM * NSP;
    const size_t sNN = (size_t)NSP * NSP;
    const float attn_scale = 0.04419417382415922f;  // 1/sqrt(512)

    const int smem00 = NSTAGE * (BM * 20 + BK * 136) * 4;  // 56832
    const int smem10 = NSTAGE * (BK * 136 + BK * 136) * 4; // 52224
    const int smem01 = NSTAGE * (BM * 20 + BN * 20) * 4;   // 61440
    cudaFuncSetAttribute(gemm_tc<0,0,0>, cudaFuncAttributeMaxDynamicSharedMemorySize, smem00);
    cudaFuncSetAttribute(gemm_tc<1,0,1>, cudaFuncAttributeMaxDynamicSharedMemorySize, smem10);
    cudaFuncSetAttribute(gemm_tc<0,1,4>, cudaFuncAttributeMaxDynamicSharedMemorySize, smem01);
    cudaFuncSetAttribute(gemm_tc<0,0,3>, cudaFuncAttributeMaxDynamicSharedMemorySize, smem00);

    gn_kernel<<<BDIM * GROUPS, 512>>>(x, gn_w, gn_b, hn);

    dim3 blk(256);
    dim3 gp(NSP / BN, CDIM / BM, BDIM);   // 32 x 4 x 2
    dim3 gs(NSP / BN, NSP / BM, BDIM);    // 32 x 32 x 2

    // Q/K/V projections
    gemm_tc<0,0,0><<<gp, blk, smem00>>>(wq, hn, q, CDIM, CDIM, NSP, NSP,
                                        0, sCN, sCN, bq, 1.f, nullptr, nullptr);
    gemm_tc<0,0,0><<<gp, blk, smem00>>>(wk, hn, k, CDIM, CDIM, NSP, NSP,
                                        0, sCN, sCN, bk, 1.f, nullptr, nullptr);
    gemm_tc<0,0,0><<<gp, blk, smem00>>>(wv, hn, v, CDIM, CDIM, NSP, NSP,
                                        0, sCN, sCN, bv, 1.f, nullptr, nullptr);

    // e[i,j] = exp(q.k / sqrt(C))   (fused exp epilogue)
    gemm_tc<1,0,1><<<gs, blk, smem10>>>(q, k, s, CDIM, NSP, NSP, NSP,
                                        sCN, sCN, sNN, nullptr, attn_scale,
                                        nullptr, nullptr);

    rowsum_kernel<<<BDIM * NSP, 256>>>(s, rs);

    // o[c,i] = (sum_j v[c,j] e[i,j]) * inv_rowsum[i]
    gemm_tc<0,1,4><<<gp, blk, smem01>>>(v, s, o, NSP, NSP, NSP, NSP,
                                        sCN, sNN, sCN, nullptr, 1.f,
                                        nullptr, rs);

    // out = x + wp @ o + bp
    gemm_tc<0,0,3><<<gp, blk, smem00>>>(wp, o, out, CDIM, CDIM, NSP, NSP,
                                        0, sCN, sCN, bp, 1.f, x, nullptr);
}

// round 10
// speedup vs baseline: 6.4917x; 1.8631x over previous
#include <cuda_runtime.h>
#include <cuda_fp16.h>
#include <cstdint>
#include <math.h>

#define BDIM 2
#define CDIM 512
#define NSP  4096
#define GROUPS 32
#define CPG  16

// ---- static scratch (fp16, all [row][col] with col contiguous) ----
__device__ __half g_hnT[(size_t)BDIM * NSP * CDIM];  // [b][n][c]
__device__ __half g_qT [(size_t)BDIM * NSP * CDIM];  // [b][n][c]
__device__ __half g_kT [(size_t)BDIM * NSP * CDIM];  // [b][n][c]
__device__ __half g_v  [(size_t)BDIM * CDIM * NSP];  // [b][c][n]
__device__ __half g_oT [(size_t)BDIM * NSP * CDIM];  // [b][n][c]
__device__ __half g_s  [(size_t)BDIM * NSP * NSP];   // [b][i][j] exp-scores
__device__ float  g_rs [(size_t)BDIM * NSP];         // 1/rowsum
__device__ __half g_wq [CDIM * CDIM];
__device__ __half g_wk [CDIM * CDIM];
__device__ __half g_wv [CDIM * CDIM];
__device__ __half g_wp [CDIM * CDIM];

// ---------------- reductions ----------------
__device__ __forceinline__ float blockReduceSum(float v, float* sh) {
    #pragma unroll
    for (int o = 16; o; o >>= 1) v += __shfl_down_sync(0xffffffffu, v, o);
    int lane = threadIdx.x & 31, wid = threadIdx.x >> 5;
    if (lane == 0) sh[wid] = v;
    __syncthreads();
    int nw = blockDim.x >> 5;
    v = (threadIdx.x < nw) ? sh[threadIdx.x] : 0.f;
    if (wid == 0) {
        #pragma unroll
        for (int o = 16; o; o >>= 1) v += __shfl_down_sync(0xffffffffu, v, o);
    }
    return v;
}

// ---------------- weight fp32 -> fp16 ----------------
__global__ void __launch_bounds__(256)
w2h4(const float* __restrict__ a, const float* __restrict__ b,
     const float* __restrict__ c, const float* __restrict__ d,
     __half* __restrict__ A, __half* __restrict__ B,
     __half* __restrict__ C, __half* __restrict__ D) {
    int i = blockIdx.x * 256 + threadIdx.x;
    if (i < CDIM * CDIM) {
        A[i] = __float2half_rn(a[i]);
        B[i] = __float2half_rn(b[i]);
        C[i] = __float2half_rn(c[i]);
        D[i] = __float2half_rn(d[i]);
    }
}

// ---------------- GroupNorm -> transposed fp16 hnT[n][c] ----------------
__global__ void __launch_bounds__(512)
gn_kernel(const float* __restrict__ x, const float* __restrict__ w,
          const float* __restrict__ bb, __half* __restrict__ hnT) {
    __shared__ float sh[32];
    __shared__ float st[2];
    __shared__ float tile[16][129];
    int blk = blockIdx.x;
    int b = blk / GROUPS, g = blk % GROUPS;
    const float* xp = x + ((size_t)b * CDIM + (size_t)g * CPG) * NSP;
    int tid = threadIdx.x;

    float s = 0.f, ss = 0.f;
    for (int i = tid; i < 16384; i += 512) {
        float4 v = reinterpret_cast<const float4*>(xp)[i];
        s  += v.x + v.y + v.z + v.w;
        ss += v.x * v.x + v.y * v.y + v.z * v.z + v.w * v.w;
    }
    float tot = blockReduceSum(s, sh);
    __syncthreads();
    float tot2 = blockReduceSum(ss, sh);
    if (tid == 0) {
        float mean = tot / 65536.f;
        float var  = tot2 / 65536.f - mean * mean;
        st[0] = mean; st[1] = rsqrtf(var + 1e-6f);
    }
    __syncthreads();
    float mean = st[0], rstd = st[1];

    __half* hT = hnT + (size_t)b * NSP * CDIM;
    int cl = tid >> 7, nl = tid & 127;   // read: 4 chans x 128 n
    int nw = tid >> 2, cq = tid & 3;     // write: n row, 4-chan group

    for (int n0 = 0; n0 < NSP; n0 += 128) {
        #pragma unroll
        for (int j = 0; j < 4; j++) {
            int c = cl * 4 + j;
            float v = xp[(size_t)c * NSP + n0 + nl];
            tile[c][nl] = (v - mean) * rstd * w[g * CPG + c] + bb[g * CPG + c];
        }
        __syncthreads();
        __half2 h0 = __floats2half2_rn(tile[cq * 4 + 0][nw], tile[cq * 4 + 1][nw]);
        __half2 h1 = __floats2half2_rn(tile[cq * 4 + 2][nw], tile[cq * 4 + 3][nw]);
        __half2* dst = reinterpret_cast<__half2*>(
            &hT[(size_t)(n0 + nw) * CDIM + g * CPG + cq * 4]);
        dst[0] = h0; dst[1] = h1;
        __syncthreads();
    }
}

// ---------------- fp16 tensor-core GEMM (ldmatrix + m16n8k16) ----------------
__device__ __forceinline__ void mma_f16(float* c, const uint32_t* a, const uint32_t* b) {
    asm volatile(
        "mma.sync.aligned.m16n8k16.row.col.f32.f16.f16.f32 "
        "{%0,%1,%2,%3}, {%4,%5,%6,%7}, {%8,%9}, {%0,%1,%2,%3};"
        : "+f"(c[0]), "+f"(c[1]), "+f"(c[2]), "+f"(c[3])
        : "r"(a[0]), "r"(a[1]), "r"(a[2]), "r"(a[3]), "r"(b[0]), "r"(b[1]));
}
__device__ __forceinline__ void ldmx4(uint32_t* r, uint32_t addr) {
    asm volatile("ldmatrix.sync.aligned.m8n8.x4.shared.b16 {%0,%1,%2,%3}, [%4];"
                 : "=r"(r[0]), "=r"(r[1]), "=r"(r[2]), "=r"(r[3]) : "r"(addr));
}
__device__ __forceinline__ void cpasync16(uint32_t dst, const void* src) {
    asm volatile("cp.async.cg.shared.global [%0], [%1], 16;\n" :: "r"(dst), "l"(src));
}
__device__ __forceinline__ void cp_commit() {
    asm volatile("cp.async.commit_group;\n" ::: "memory");
}

// D[m][n] = sum_k A[m][k]*B[n][k]  (both fp16, K-contiguous)
// EPI: 0:+aux[ncol] fp16out  1:+aux[m] fp16out  2:exp(v*scale) fp16out
//      3:*aux[bz*NSP+m] fp16out  4:+aux[m]+resid fp32out
#define BM 128
#define BN 128
#define BK 32
#define RSTR 80                 // smem row stride bytes (32 halves + pad)
#define TSTR (128 * RSTR)       // 10240 per operand tile
#define STGB (2 * TSTR)         // 20480 per stage
#define NSTAGE 3

template<int EPI>
__global__ void __launch_bounds__(256, 2)
gemm_h(const __half* __restrict__ A, const __half* __restrict__ B, void* __restrict__ Cv,
       int K, int lda, int ldb, int ldc, size_t sA, size_t sB, size_t sC,
       const float* __restrict__ aux, const float* __restrict__ resid, float scale) {
    extern __shared__ char dsm[];
    int bz = blockIdx.z;
    A += sA * (size_t)bz;
    B += sB * (size_t)bz;

    const int m0 = blockIdx.y * BM;
    const int n0 = blockIdx.x * BN;
    int t = threadIdx.x, wid = t >> 5, lane = t & 31;
    int wm = wid >> 2, wn = wid & 3;     // 2 x 4 warp grid; warp tile 64x32
    int gr = lane >> 2, gc = lane & 3;

    uint32_t sbase = ((uint32_t)__cvta_generic_to_shared(dsm) + 127u) & ~127u;

    // fill coords: 512 chunks per operand, 2 per thread each
    int f_r[2], f_c[2];
    #pragma unroll
    for (int i = 0; i < 2; i++) {
        int q = t + i * 256;
        f_r[i] = q >> 2; f_c[i] = q & 3;
    }
    auto fill = [&](int kb, int stg) {
        uint32_t ab = sbase + stg * STGB;
        uint32_t bbs = ab + TSTR;
        const __half* Ak = A + (size_t)m0 * lda + kb * BK;
        const __half* Bk = B + (size_t)n0 * ldb + kb * BK;
        #pragma unroll
        for (int i = 0; i < 2; i++)
            cpasync16(ab + f_r[i] * RSTR + f_c[i] * 16,
                      Ak + (size_t)f_r[i] * lda + f_c[i] * 8);
        #pragma unroll
        for (int i = 0; i < 2; i++)
            cpasync16(bbs + f_r[i] * RSTR + f_c[i] * 16,
                      Bk + (size_t)f_r[i] * ldb + f_c[i] * 8);
    };

    // ldmatrix per-thread address offsets (within a stage)
    // A: rows m0w + (lane&15), chunk lane>>4
    uint32_t a_off = (uint32_t)((wm * 64 + (lane & 15)) * RSTR + (lane >> 4) * 16);
    // B: rows n0w + (lane&7) + ((lane>>4)<<3), chunk (lane>>3)&1
    uint32_t b_off = (uint32_t)(TSTR + (wn * 32 + (lane & 7) + ((lane >> 4) << 3)) * RSTR
                                + (((lane >> 3) & 1) * 16));

    float acc[4][4][4];
    #pragma unroll
    for (int i = 0; i < 4; i++)
        #pragma unroll
        for (int j = 0; j < 4; j++)
            #pragma unroll
            for (int r = 0; r < 4; r++) acc[i][j][r] = 0.f;

    const int nk = K / BK;
    fill(0, 0); cp_commit();
    fill(1, 1); cp_commit();

    int st_cur = 0, st_nxt = 2;
    for (int kb = 0; kb < nk; kb++) {
        asm volatile("cp.async.wait_group 1;\n" ::: "memory");
        __syncthreads();
        if (kb + 2 < nk) fill(kb + 2, st_nxt);
        cp_commit();

        uint32_t abase = sbase + st_cur * STGB + a_off;
        uint32_t bbase = sbase + st_cur * STGB + b_off;

        #pragma unroll
        for (int kk = 0; kk < 2; kk++) {        // two k16 steps
            uint32_t af[4][4];
            #pragma unroll
            for (int mt = 0; mt < 4; mt++)
                ldmx4(af[mt], abase + mt * (16 * RSTR) + kk * 32);
            uint32_t bf[2][4];                   // each covers 2 n-tiles
            #pragma unroll
            for (int j = 0; j < 2; j++)
                ldmx4(bf[j], bbase + j * (16 * RSTR) + kk * 32);
            #pragma unroll
            for (int mt = 0; mt < 4; mt++)
                #pragma unroll
                for (int nt = 0; nt < 4; nt++)
                    mma_f16(acc[mt][nt], af[mt], &bf[nt >> 1][(nt & 1) * 2]);
        }
        st_cur = (st_cur == NSTAGE - 1) ? 0 : st_cur + 1;
        st_nxt = (st_nxt == NSTAGE - 1) ? 0 : st_nxt + 1;
    }

    // ---- epilogue ----
    // acc regs: c0,c1 = (gr, 2gc..2gc+1), c2,c3 = (gr+8, ...)
    #pragma unroll
    for (int mt = 0; mt < 4; mt++) {
        int mA = m0 + wm * 64 + mt * 16 + gr;
        int mB = mA + 8;
        float bA = 0.f, bB = 0.f;
        if (EPI == 1 || EPI == 4) { bA = aux[mA]; bB = aux[mB]; }
        if (EPI == 3) { bA = aux[(size_t)bz * NSP + mA]; bB = aux[(size_t)bz * NSP + mB]; }
        #pragma unroll
        for (int nt = 0; nt < 4; nt++) {
            int n = n0 + wn * 32 + nt * 8 + 2 * gc;
            float v0 = acc[mt][nt][0], v1 = acc[mt][nt][1];
            float v2 = acc[mt][nt][2], v3 = acc[mt][nt][3];
            if (EPI == 0) {
                float c0 = aux[n], c1 = aux[n + 1];
                v0 += c0; v1 += c1; v2 += c0; v3 += c1;
            }
            if (EPI == 1) { v0 += bA; v1 += bA; v2 += bB; v3 += bB; }
            if (EPI == 2) {
                v0 = __expf(v0 * scale); v1 = __expf(v1 * scale);
                v2 = __expf(v2 * scale); v3 = __expf(v3 * scale);
            }
            if (EPI == 3) { v0 *= bA; v1 *= bA; v2 *= bB; v3 *= bB; }
            if (EPI == 4) {
                const float* rp = resid + sC * (size_t)bz;
                float2 r0 = *reinterpret_cast<const float2*>(&rp[(size_t)mA * ldc + n]);
                float2 r1 = *reinterpret_cast<const float2*>(&rp[(size_t)mB * ldc + n]);
                v0 += bA + r0.x; v1 += bA + r0.y; v2 += bB + r1.x; v3 += bB + r1.y;
            }
            if (EPI == 4) {
                float* C = (float*)Cv + sC * (size_t)bz;
                *reinterpret_cast<float2*>(&C[(size_t)mA * ldc + n]) = make_float2(v0, v1);
                *reinterpret_cast<float2*>(&C[(size_t)mB * ldc + n]) = make_float2(v2, v3);
            } else {
                __half* C = (__half*)Cv + sC * (size_t)bz;
                *reinterpret_cast<__half2*>(&C[(size_t)mA * ldc + n]) = __floats2half2_rn(v0, v1);
                *reinterpret_cast<__half2*>(&C[(size_t)mB * ldc + n]) = __floats2half2_rn(v2, v3);
            }
        }
    }
}

// ---------------- row-sum reciprocal (fp16 input) ----------------
__global__ void __launch_bounds__(256)
rowsum_kernel(const __half* __restrict__ s, float* __restrict__ inv) {
    __shared__ float sh[32];
    size_t row = blockIdx.x;
    const __half* p = s + row * (size_t)NSP;
    int tid = threadIdx.x;
    float sum = 0.f;
    #pragma unroll
    for (int it = 0; it < 2; it++) {
        uint4 u = reinterpret_cast<const uint4*>(p)[tid + it * 256];
        __half2 h0 = *reinterpret_cast<__half2*>(&u.x);
        __half2 h1 = *reinterpret_cast<__half2*>(&u.y);
        __half2 h2 = *reinterpret_cast<__half2*>(&u.z);
        __half2 h3 = *reinterpret_cast<__half2*>(&u.w);
        float2 f0 = __half22float2(h0), f1 = __half22float2(h1);
        float2 f2 = __half22float2(h2), f3 = __half22float2(h3);
        sum += f0.x + f0.y + f1.x + f1.y + f2.x + f2.y + f3.x + f3.y;
    }
    sum = blockReduceSum(sum, sh);
    if (tid == 0) inv[row] = 1.f / sum;
}

// ---------------- launcher ----------------
extern "C" void kernel_launch(void* const* d_in, const int* in_sizes, int n_in,
                              void* d_out, int out_size) {
    const float* x    = (const float*)d_in[0];
    const float* gn_w = (const float*)d_in[1];
    const float* gn_b = (const float*)d_in[2];
    const float* wq   = (const float*)d_in[3];
    const float* bq   = (const float*)d_in[4];
    const float* wk   = (const float*)d_in[5];
    const float* bk   = (const float*)d_in[6];
    const float* wv   = (const float*)d_in[7];
    const float* bv   = (const float*)d_in[8];
    const float* wp   = (const float*)d_in[9];
    const float* bp   = (const float*)d_in[10];
    float* out = (float*)d_out;

    __half *hnT, *qT, *kT, *v, *oT, *s, *wqh, *wkh, *wvh, *wph;
    float *rs;
    cudaGetSymbolAddress((void**)&hnT, g_hnT);
    cudaGetSymbolAddress((void**)&qT,  g_qT);
    cudaGetSymbolAddress((void**)&kT,  g_kT);
    cudaGetSymbolAddress((void**)&v,   g_v);
    cudaGetSymbolAddress((void**)&oT,  g_oT);
    cudaGetSymbolAddress((void**)&s,   g_s);
    cudaGetSymbolAddress((void**)&rs,  g_rs);
    cudaGetSymbolAddress((void**)&wqh, g_wq);
    cudaGetSymbolAddress((void**)&wkh, g_wk);
    cudaGetSymbolAddress((void**)&wvh, g_wv);
    cudaGetSymbolAddress((void**)&wph, g_wp);

    const size_t CN = (size_t)NSP * CDIM;
    const size_t NN = (size_t)NSP * NSP;
    const float attn_scale = 0.04419417382415922f;  // 1/sqrt(512)
    const int smem = NSTAGE * STGB + 256;           // 61696

    cudaFuncSetAttribute(gemm_h<0>, cudaFuncAttributeMaxDynamicSharedMemorySize, smem);
    cudaFuncSetAttribute(gemm_h<1>, cudaFuncAttributeMaxDynamicSharedMemorySize, smem);
    cudaFuncSetAttribute(gemm_h<2>, cudaFuncAttributeMaxDynamicSharedMemorySize, smem);
    cudaFuncSetAttribute(gemm_h<3>, cudaFuncAttributeMaxDynamicSharedMemorySize, smem);
    cudaFuncSetAttribute(gemm_h<4>, cudaFuncAttributeMaxDynamicSharedMemorySize, smem);

    w2h4<<<(CDIM * CDIM + 255) / 256, 256>>>(wq, wk, wv, wp, wqh, wkh, wvh, wph);
    gn_kernel<<<BDIM * GROUPS, 512>>>(x, gn_w, gn_b, hnT);

    dim3 blk(256);
    // qT[n][o] = sum_c hnT[n][c] wq[o][c] + bq[o]      M=NSP,N=CDIM
    gemm_h<0><<<dim3(4, 32, BDIM), blk, smem>>>(
        hnT, wqh, qT, CDIM, CDIM, CDIM, CDIM, CN, 0, CN, bq, nullptr, 0.f);
    gemm_h<0><<<dim3(4, 32, BDIM), blk, smem>>>(
        hnT, wkh, kT, CDIM, CDIM, CDIM, CDIM, CN, 0, CN, bk, nullptr, 0.f);
    // v[c][n] = sum_k wv[c][k] hnT[n][k] + bv[c]       M=CDIM,N=NSP
    gemm_h<1><<<dim3(32, 4, BDIM), blk, smem>>>(
        wvh, hnT, v, CDIM, CDIM, CDIM, NSP, 0, CN, CN, bv, nullptr, 0.f);
    // s[i][j] = exp(sum_c qT[i][c] kT[j][c] * scale)   M=N=NSP
    gemm_h<2><<<dim3(32, 32, BDIM), blk, smem>>>(
        qT, kT, s, CDIM, CDIM, CDIM, NSP, CN, CN, NN, nullptr, nullptr, attn_scale);

    rowsum_kernel<<<BDIM * NSP, 256>>>(s, rs);

    // oT[i][c] = (sum_j s[i][j] v[c][j]) * rs[b][i]    M=NSP,N=CDIM
    gemm_h<3><<<dim3(4, 32, BDIM), blk, smem>>>(
        s, v, oT, NSP, NSP, NSP, CDIM, NN, CN, CN, rs, nullptr, 0.f);
    // out[o][n] = sum_c wp[o][c] oT[n][c] + bp[o] + x  M=CDIM,N=NSP  (fp32 out)
    gemm_h<4><<<dim3(32, 4, BDIM), blk, smem>>>(
        wph, oT, out, CDIM, CDIM, CDIM, NSP, 0, CN, CN, bp, x, 0.f);
}

// round 11
// speedup vs baseline: 6.4992x; 1.0011x over previous
#include <cuda_runtime.h>
#include <cuda_fp16.h>
#include <cstdint>
#include <math.h>

#define BDIM 2
#define CDIM 512
#define NSP  4096
#define GROUPS 32
#define CPG  16

// ---- static scratch ----
__device__ __half g_hnT[(size_t)BDIM * NSP * CDIM];   // [b][n][c]
__device__ __half g_qkT[(size_t)BDIM * NSP * 1024];   // [b][n][q:512|k:512]
__device__ __half g_v  [(size_t)BDIM * CDIM * NSP];   // [b][c][n]
__device__ __half g_oT [(size_t)BDIM * NSP * CDIM];   // [b][n][c]
__device__ __half g_s  [(size_t)BDIM * NSP * NSP];    // [b][i][j] exp-scores
__device__ float  g_rs [(size_t)BDIM * NSP];          // 1/rowsum
__device__ __half g_wqk[1024 * CDIM];                 // rows 0-511 wq, 512-1023 wk
__device__ float  g_bqk[1024];
__device__ __half g_wv [CDIM * CDIM];
__device__ __half g_wp [CDIM * CDIM];

// ---------------- reductions ----------------
__device__ __forceinline__ float blockReduceSum(float v, float* sh) {
    #pragma unroll
    for (int o = 16; o; o >>= 1) v += __shfl_down_sync(0xffffffffu, v, o);
    int lane = threadIdx.x & 31, wid = threadIdx.x >> 5;
    if (lane == 0) sh[wid] = v;
    __syncthreads();
    int nw = blockDim.x >> 5;
    v = (threadIdx.x < nw) ? sh[threadIdx.x] : 0.f;
    if (wid == 0) {
        #pragma unroll
        for (int o = 16; o; o >>= 1) v += __shfl_down_sync(0xffffffffu, v, o);
    }
    return v;
}

// ---------------- weights fp32->fp16 (+ q|k concat) ----------------
__global__ void __launch_bounds__(256)
w2h(const float* __restrict__ wq, const float* __restrict__ wk,
    const float* __restrict__ wv, const float* __restrict__ wp,
    const float* __restrict__ bq, const float* __restrict__ bk,
    __half* __restrict__ Wqk, __half* __restrict__ Wv,
    __half* __restrict__ Wp, float* __restrict__ Bqk) {
    int i = blockIdx.x * 256 + threadIdx.x;
    if (i < CDIM * CDIM) {
        Wqk[i] = __float2half_rn(wq[i]);
        Wqk[i + CDIM * CDIM] = __float2half_rn(wk[i]);
        Wv[i] = __float2half_rn(wv[i]);
        Wp[i] = __float2half_rn(wp[i]);
    }
    if (i < CDIM) { Bqk[i] = bq[i]; Bqk[i + CDIM] = bk[i]; }
}

// ---------------- GroupNorm -> transposed fp16 hnT[n][c] ----------------
__global__ void __launch_bounds__(512)
gn_kernel(const float* __restrict__ x, const float* __restrict__ w,
          const float* __restrict__ bb, __half* __restrict__ hnT) {
    __shared__ float sh[32];
    __shared__ float st[2];
    __shared__ float tile[16][129];
    int blk = blockIdx.x;
    int b = blk / GROUPS, g = blk % GROUPS;
    const float* xp = x + ((size_t)b * CDIM + (size_t)g * CPG) * NSP;
    int tid = threadIdx.x;

    float s = 0.f, ss = 0.f;
    for (int i = tid; i < 16384; i += 512) {
        float4 v = reinterpret_cast<const float4*>(xp)[i];
        s  += v.x + v.y + v.z + v.w;
        ss += v.x * v.x + v.y * v.y + v.z * v.z + v.w * v.w;
    }
    float tot = blockReduceSum(s, sh);
    __syncthreads();
    float tot2 = blockReduceSum(ss, sh);
    if (tid == 0) {
        float mean = tot / 65536.f;
        float var  = tot2 / 65536.f - mean * mean;
        st[0] = mean; st[1] = rsqrtf(var + 1e-6f);
    }
    __syncthreads();
    float mean = st[0], rstd = st[1];

    __half* hT = hnT + (size_t)b * NSP * CDIM;
    int cl = tid >> 7, nl = tid & 127;
    int nw = tid >> 2, cq = tid & 3;

    for (int n0 = 0; n0 < NSP; n0 += 128) {
        #pragma unroll
        for (int j = 0; j < 4; j++) {
            int c = cl * 4 + j;
            float v = xp[(size_t)c * NSP + n0 + nl];
            tile[c][nl] = (v - mean) * rstd * w[g * CPG + c] + bb[g * CPG + c];
        }
        __syncthreads();
        __half2 h0 = __floats2half2_rn(tile[cq * 4 + 0][nw], tile[cq * 4 + 1][nw]);
        __half2 h1 = __floats2half2_rn(tile[cq * 4 + 2][nw], tile[cq * 4 + 3][nw]);
        __half2* dst = reinterpret_cast<__half2*>(
            &hT[(size_t)(n0 + nw) * CDIM + g * CPG + cq * 4]);
        dst[0] = h0; dst[1] = h1;
        __syncthreads();
    }
}

// ---------------- fp16 tensor-core GEMM, 128 threads / 128x64 tile ----------------
__device__ __forceinline__ void mma_f16(float* c, const uint32_t* a, const uint32_t* b) {
    asm volatile(
        "mma.sync.aligned.m16n8k16.row.col.f32.f16.f16.f32 "
        "{%0,%1,%2,%3}, {%4,%5,%6,%7}, {%8,%9}, {%0,%1,%2,%3};"
        : "+f"(c[0]), "+f"(c[1]), "+f"(c[2]), "+f"(c[3])
        : "r"(a[0]), "r"(a[1]), "r"(a[2]), "r"(a[3]), "r"(b[0]), "r"(b[1]));
}
__device__ __forceinline__ void ldmx4(uint32_t* r, uint32_t addr) {
    asm volatile("ldmatrix.sync.aligned.m8n8.x4.shared.b16 {%0,%1,%2,%3}, [%4];"
                 : "=r"(r[0]), "=r"(r[1]), "=r"(r[2]), "=r"(r[3]) : "r"(addr));
}
__device__ __forceinline__ void cpasync16(uint32_t dst, const void* src) {
    asm volatile("cp.async.cg.shared.global [%0], [%1], 16;\n" :: "r"(dst), "l"(src));
}
__device__ __forceinline__ void cp_commit() {
    asm volatile("cp.async.commit_group;\n" ::: "memory");
}

// D[m][n] = sum_k A[m][k]*B[n][k]  (fp16, K-contiguous rows)
// EPI: 0:+aux[n] fp16  1:+aux[m] fp16  2:exp(v*scale) fp16
//      3:*aux[bz*NSP+m] fp16  4:+aux[m]+resid fp32
#define BM 128
#define BN 64
#define BK 32
#define RSTR 80
#define ATSZ (128 * RSTR)        // 10240
#define BTSZ (64 * RSTR)         // 5120
#define STGB (ATSZ + BTSZ)       // 15360
#define NSTAGE 3

template<int EPI>
__global__ void __launch_bounds__(128, 4)
gemm_h(const __half* __restrict__ A, const __half* __restrict__ B, void* __restrict__ Cv,
       int K, int lda, int ldb, int ldc, size_t sA, size_t sB, size_t sC,
       const float* __restrict__ aux, const float* __restrict__ resid, float scale) {
    extern __shared__ char dsm[];
    int bz = blockIdx.z;
    A += sA * (size_t)bz;
    B += sB * (size_t)bz;

    const int m0 = blockIdx.y * BM;
    const int n0 = blockIdx.x * BN;
    int t = threadIdx.x, wid = t >> 5, lane = t & 31;
    int wm = wid >> 1, wn = wid & 1;     // 2 x 2 warps; warp tile 64x32
    int gr = lane >> 2, gc = lane & 3;

    uint32_t sbase = ((uint32_t)__cvta_generic_to_shared(dsm) + 127u) & ~127u;

    auto fill = [&](int kb, int stg) {
        uint32_t ab = sbase + stg * STGB;
        uint32_t bbs = ab + ATSZ;
        const __half* Ak = A + (size_t)m0 * lda + kb * BK;
        const __half* Bk = B + (size_t)n0 * ldb + kb * BK;
        #pragma unroll
        for (int i = 0; i < 4; i++) {        // A: 512 chunks
            int q = t + i * 128;
            int r = q >> 2, c = q & 3;
            cpasync16(ab + r * RSTR + c * 16, Ak + (size_t)r * lda + c * 8);
        }
        #pragma unroll
        for (int i = 0; i < 2; i++) {        // B: 256 chunks
            int q = t + i * 128;
            int r = q >> 2, c = q & 3;
            cpasync16(bbs + r * RSTR + c * 16, Bk + (size_t)r * ldb + c * 8);
        }
    };

    uint32_t a_off = (uint32_t)((wm * 64 + (lane & 15)) * RSTR + (lane >> 4) * 16);
    uint32_t b_off = (uint32_t)(ATSZ + (wn * 32 + (lane & 7) + ((lane >> 4) << 3)) * RSTR
                                + (((lane >> 3) & 1) * 16));

    float acc[4][4][4];
    #pragma unroll
    for (int i = 0; i < 4; i++)
        #pragma unroll
        for (int j = 0; j < 4; j++)
            #pragma unroll
            for (int r = 0; r < 4; r++) acc[i][j][r] = 0.f;

    const int nk = K / BK;
    fill(0, 0); cp_commit();
    fill(1, 1); cp_commit();

    int st_cur = 0, st_nxt = 2;
    for (int kb = 0; kb < nk; kb++) {
        asm volatile("cp.async.wait_group 1;\n" ::: "memory");
        __syncthreads();
        if (kb + 2 < nk) fill(kb + 2, st_nxt);
        cp_commit();

        uint32_t abase = sbase + st_cur * STGB + a_off;
        uint32_t bbase = sbase + st_cur * STGB + b_off;

        #pragma unroll
        for (int kk = 0; kk < 2; kk++) {
            uint32_t af[4][4];
            #pragma unroll
            for (int mt = 0; mt < 4; mt++)
                ldmx4(af[mt], abase + mt * (16 * RSTR) + kk * 32);
            uint32_t bf[2][4];
            #pragma unroll
            for (int j = 0; j < 2; j++)
                ldmx4(bf[j], bbase + j * (16 * RSTR) + kk * 32);
            #pragma unroll
            for (int mt = 0; mt < 4; mt++)
                #pragma unroll
                for (int nt = 0; nt < 4; nt++)
                    mma_f16(acc[mt][nt], af[mt], &bf[nt >> 1][(nt & 1) * 2]);
        }
        st_cur = (st_cur == NSTAGE - 1) ? 0 : st_cur + 1;
        st_nxt = (st_nxt == NSTAGE - 1) ? 0 : st_nxt + 1;
    }

    // ---- epilogue ----
    #pragma unroll
    for (int mt = 0; mt < 4; mt++) {
        int mA = m0 + wm * 64 + mt * 16 + gr;
        int mB = mA + 8;
        float bA = 0.f, bB = 0.f;
        if (EPI == 1 || EPI == 4) { bA = aux[mA]; bB = aux[mB]; }
        if (EPI == 3) { bA = aux[(size_t)bz * NSP + mA]; bB = aux[(size_t)bz * NSP + mB]; }
        #pragma unroll
        for (int nt = 0; nt < 4; nt++) {
            int n = n0 + wn * 32 + nt * 8 + 2 * gc;
            float v0 = acc[mt][nt][0], v1 = acc[mt][nt][1];
            float v2 = acc[mt][nt][2], v3 = acc[mt][nt][3];
            if (EPI == 0) {
                float c0 = aux[n], c1 = aux[n + 1];
                v0 += c0; v1 += c1; v2 += c0; v3 += c1;
            }
            if (EPI == 1) { v0 += bA; v1 += bA; v2 += bB; v3 += bB; }
            if (EPI == 2) {
                v0 = __expf(v0 * scale); v1 = __expf(v1 * scale);
                v2 = __expf(v2 * scale); v3 = __expf(v3 * scale);
            }
            if (EPI == 3) { v0 *= bA; v1 *= bA; v2 *= bB; v3 *= bB; }
            if (EPI == 4) {
                const float* rp = resid + sC * (size_t)bz;
                float2 r0 = *reinterpret_cast<const float2*>(&rp[(size_t)mA * ldc + n]);
                float2 r1 = *reinterpret_cast<const float2*>(&rp[(size_t)mB * ldc + n]);
                v0 += bA + r0.x; v1 += bA + r0.y; v2 += bB + r1.x; v3 += bB + r1.y;
            }
            if (EPI == 4) {
                float* C = (float*)Cv + sC * (size_t)bz;
                *reinterpret_cast<float2*>(&C[(size_t)mA * ldc + n]) = make_float2(v0, v1);
                *reinterpret_cast<float2*>(&C[(size_t)mB * ldc + n]) = make_float2(v2, v3);
            } else {
                __half* C = (__half*)Cv + sC * (size_t)bz;
                *reinterpret_cast<__half2*>(&C[(size_t)mA * ldc + n]) = __floats2half2_rn(v0, v1);
                *reinterpret_cast<__half2*>(&C[(size_t)mB * ldc + n]) = __floats2half2_rn(v2, v3);
            }
        }
    }
}

// ---------------- row-sum reciprocal ----------------
__global__ void __launch_bounds__(256)
rowsum_kernel(const __half* __restrict__ s, float* __restrict__ inv) {
    __shared__ float sh[32];
    size_t row = blockIdx.x;
    const __half* p = s + row * (size_t)NSP;
    int tid = threadIdx.x;
    float sum = 0.f;
    #pragma unroll
    for (int it = 0; it < 2; it++) {
        uint4 u = reinterpret_cast<const uint4*>(p)[tid + it * 256];
        __half2 h0 = *reinterpret_cast<__half2*>(&u.x);
        __half2 h1 = *reinterpret_cast<__half2*>(&u.y);
        __half2 h2 = *reinterpret_cast<__half2*>(&u.z);
        __half2 h3 = *reinterpret_cast<__half2*>(&u.w);
        float2 f0 = __half22float2(h0), f1 = __half22float2(h1);
        float2 f2 = __half22float2(h2), f3 = __half22float2(h3);
        sum += f0.x + f0.y + f1.x + f1.y + f2.x + f2.y + f3.x + f3.y;
    }
    sum = blockReduceSum(sum, sh);
    if (tid == 0) inv[row] = 1.f / sum;
}

// ---------------- launcher ----------------
extern "C" void kernel_launch(void* const* d_in, const int* in_sizes, int n_in,
                              void* d_out, int out_size) {
    const float* x    = (const float*)d_in[0];
    const float* gn_w = (const float*)d_in[1];
    const float* gn_b = (const float*)d_in[2];
    const float* wq   = (const float*)d_in[3];
    const float* bq   = (const float*)d_in[4];
    const float* wk   = (const float*)d_in[5];
    const float* bk   = (const float*)d_in[6];
    const float* wv   = (const float*)d_in[7];
    const float* bv   = (const float*)d_in[8];
    const float* wp   = (const float*)d_in[9];
    const float* bp   = (const float*)d_in[10];
    float* out = (float*)d_out;

    __half *hnT, *qkT, *v, *oT, *s, *wqk, *wvh, *wph;
    float *rs, *bqk;
    cudaGetSymbolAddress((void**)&hnT, g_hnT);
    cudaGetSymbolAddress((void**)&qkT, g_qkT);
    cudaGetSymbolAddress((void**)&v,   g_v);
    cudaGetSymbolAddress((void**)&oT,  g_oT);
    cudaGetSymbolAddress((void**)&s,   g_s);
    cudaGetSymbolAddress((void**)&rs,  g_rs);
    cudaGetSymbolAddress((void**)&wqk, g_wqk);
    cudaGetSymbolAddress((void**)&bqk, g_bqk);
    cudaGetSymbolAddress((void**)&wvh, g_wv);
    cudaGetSymbolAddress((void**)&wph, g_wp);

    const size_t CN  = (size_t)NSP * CDIM;
    const size_t QKN = (size_t)NSP * 1024;
    const size_t NN  = (size_t)NSP * NSP;
    const float attn_scale = 0.04419417382415922f;  // 1/sqrt(512)
    const int smem = NSTAGE * STGB + 256;           // 46336

    cudaFuncSetAttribute(gemm_h<0>, cudaFuncAttributeMaxDynamicSharedMemorySize, smem);
    cudaFuncSetAttribute(gemm_h<1>, cudaFuncAttributeMaxDynamicSharedMemorySize, smem);
    cudaFuncSetAttribute(gemm_h<2>, cudaFuncAttributeMaxDynamicSharedMemorySize, smem);
    cudaFuncSetAttribute(gemm_h<3>, cudaFuncAttributeMaxDynamicSharedMemorySize, smem);
    cudaFuncSetAttribute(gemm_h<4>, cudaFuncAttributeMaxDynamicSharedMemorySize, smem);

    w2h<<<(CDIM * CDIM + 255) / 256, 256>>>(wq, wk, wv, wp, bq, bk, wqk, wvh, wph, bqk);
    gn_kernel<<<BDIM * GROUPS, 512>>>(x, gn_w, gn_b, hnT);

    dim3 blk(128);
    // qkT[n][o] = sum_c hnT[n][c] wqk[o][c] + bqk[o]   M=NSP, N=1024
    gemm_h<0><<<dim3(1024 / BN, NSP / BM, BDIM), blk, smem>>>(
        hnT, wqk, qkT, CDIM, CDIM, CDIM, 1024, CN, 0, QKN, bqk, nullptr, 0.f);
    // v[c][n] = sum_k wv[c][k] hnT[n][k] + bv[c]       M=CDIM, N=NSP
    gemm_h<1><<<dim3(NSP / BN, CDIM / BM, BDIM), blk, smem>>>(
        wvh, hnT, v, CDIM, CDIM, CDIM, NSP, 0, CN, CN, bv, nullptr, 0.f);
    // s[i][j] = exp(sum_c qT[i][c] kT[j][c] * scale)   M=N=NSP
    gemm_h<2><<<dim3(NSP / BN, NSP / BM, BDIM), blk, smem>>>(
        qkT, qkT + CDIM, s, CDIM, 1024, 1024, NSP, QKN, QKN, NN,
        nullptr, nullptr, attn_scale);

    rowsum_kernel<<<BDIM * NSP, 256>>>(s, rs);

    // oT[i][c] = (sum_j s[i][j] v[c][j]) * rs[b][i]    M=NSP, N=CDIM
    gemm_h<3><<<dim3(CDIM / BN, NSP / BM, BDIM), blk, smem>>>(
        s, v, oT, NSP, NSP, NSP, CDIM, NN, CN, CN, rs, nullptr, 0.f);
    // out[o][n] = sum_c wp[o][c] oT[n][c] + bp[o] + x  M=CDIM, N=NSP (fp32)
    gemm_h<4><<<dim3(NSP / BN, CDIM / BM, BDIM), blk, smem>>>(
        wph, oT, out, CDIM, CDIM, CDIM, NSP, 0, CN, CN, bp, x, 0.f);
}

// round 12
// speedup vs baseline: 7.2654x; 1.1179x over previous
#include <cuda_runtime.h>
#include <cuda_fp16.h>
#include <cstdint>
#include <math.h>

#define BDIM 2
#define CDIM 512
#define NSP  4096
#define GROUPS 32
#define CPG  16

// ---- static scratch ----
__device__ __half g_hnT[(size_t)BDIM * NSP * CDIM];   // [b][n][c]
__device__ __half g_qkT[(size_t)BDIM * NSP * 1024];   // [b][n][q:512|k:512]
__device__ __half g_v  [(size_t)BDIM * CDIM * NSP];   // [b][c][n]
__device__ __half g_oT [(size_t)BDIM * NSP * CDIM];   // [b][n][c]
__device__ __half g_s  [(size_t)BDIM * NSP * NSP];    // [b][i][j] exp-scores
__device__ float  g_rsp[(size_t)BDIM * NSP * 64];     // row-sum partials [row][jb]
__device__ float  g_rs [(size_t)BDIM * NSP];          // 1/rowsum
__device__ __half g_wqk[1024 * CDIM];
__device__ float  g_bqk[1024];
__device__ __half g_wv [CDIM * CDIM];
__device__ __half g_wp [CDIM * CDIM];

// ---------------- reductions ----------------
__device__ __forceinline__ float blockReduceSum(float v, float* sh) {
    #pragma unroll
    for (int o = 16; o; o >>= 1) v += __shfl_down_sync(0xffffffffu, v, o);
    int lane = threadIdx.x & 31, wid = threadIdx.x >> 5;
    if (lane == 0) sh[wid] = v;
    __syncthreads();
    int nw = blockDim.x >> 5;
    v = (threadIdx.x < nw) ? sh[threadIdx.x] : 0.f;
    if (wid == 0) {
        #pragma unroll
        for (int o = 16; o; o >>= 1) v += __shfl_down_sync(0xffffffffu, v, o);
    }
    return v;
}

// ---------------- weights fp32->fp16 (+ q|k concat) ----------------
__global__ void __launch_bounds__(256)
w2h(const float* __restrict__ wq, const float* __restrict__ wk,
    const float* __restrict__ wv, const float* __restrict__ wp,
    const float* __restrict__ bq, const float* __restrict__ bk,
    __half* __restrict__ Wqk, __half* __restrict__ Wv,
    __half* __restrict__ Wp, float* __restrict__ Bqk) {
    int i = blockIdx.x * 256 + threadIdx.x;
    if (i < CDIM * CDIM) {
        Wqk[i] = __float2half_rn(wq[i]);
        Wqk[i + CDIM * CDIM] = __float2half_rn(wk[i]);
        Wv[i] = __float2half_rn(wv[i]);
        Wp[i] = __float2half_rn(wp[i]);
    }
    if (i < CDIM) { Bqk[i] = bq[i]; Bqk[i + CDIM] = bk[i]; }
}

// ---------------- GroupNorm -> transposed fp16 hnT[n][c] ----------------
__global__ void __launch_bounds__(512)
gn_kernel(const float* __restrict__ x, const float* __restrict__ w,
          const float* __restrict__ bb, __half* __restrict__ hnT) {
    __shared__ float sh[32];
    __shared__ float st[2];
    __shared__ float tile[16][129];
    int blk = blockIdx.x;
    int b = blk / GROUPS, g = blk % GROUPS;
    const float* xp = x + ((size_t)b * CDIM + (size_t)g * CPG) * NSP;
    int tid = threadIdx.x;

    float s = 0.f, ss = 0.f;
    for (int i = tid; i < 16384; i += 512) {
        float4 v = reinterpret_cast<const float4*>(xp)[i];
        s  += v.x + v.y + v.z + v.w;
        ss += v.x * v.x + v.y * v.y + v.z * v.z + v.w * v.w;
    }
    float tot = blockReduceSum(s, sh);
    __syncthreads();
    float tot2 = blockReduceSum(ss, sh);
    if (tid == 0) {
        float mean = tot / 65536.f;
        float var  = tot2 / 65536.f - mean * mean;
        st[0] = mean; st[1] = rsqrtf(var + 1e-6f);
    }
    __syncthreads();
    float mean = st[0], rstd = st[1];

    __half* hT = hnT + (size_t)b * NSP * CDIM;
    int cl = tid >> 7, nl = tid & 127;
    int nw = tid >> 2, cq = tid & 3;

    for (int n0 = 0; n0 < NSP; n0 += 128) {
        #pragma unroll
        for (int j = 0; j < 4; j++) {
            int c = cl * 4 + j;
            float v = xp[(size_t)c * NSP + n0 + nl];
            tile[c][nl] = (v - mean) * rstd * w[g * CPG + c] + bb[g * CPG + c];
        }
        __syncthreads();
        __half2 h0 = __floats2half2_rn(tile[cq * 4 + 0][nw], tile[cq * 4 + 1][nw]);
        __half2 h1 = __floats2half2_rn(tile[cq * 4 + 2][nw], tile[cq * 4 + 3][nw]);
        __half2* dst = reinterpret_cast<__half2*>(
            &hT[(size_t)(n0 + nw) * CDIM + g * CPG + cq * 4]);
        dst[0] = h0; dst[1] = h1;
        __syncthreads();
    }
}

// ---------------- fp16 tensor-core GEMM, 128thr / 128x64 tile / BK=64 ----------------
__device__ __forceinline__ void mma_f16(float* c, const uint32_t* a, const uint32_t* b) {
    asm volatile(
        "mma.sync.aligned.m16n8k16.row.col.f32.f16.f16.f32 "
        "{%0,%1,%2,%3}, {%4,%5,%6,%7}, {%8,%9}, {%0,%1,%2,%3};"
        : "+f"(c[0]), "+f"(c[1]), "+f"(c[2]), "+f"(c[3])
        : "r"(a[0]), "r"(a[1]), "r"(a[2]), "r"(a[3]), "r"(b[0]), "r"(b[1]));
}
__device__ __forceinline__ void ldmx4(uint32_t* r, uint32_t addr) {
    asm volatile("ldmatrix.sync.aligned.m8n8.x4.shared.b16 {%0,%1,%2,%3}, [%4];"
                 : "=r"(r[0]), "=r"(r[1]), "=r"(r[2]), "=r"(r[3]) : "r"(addr));
}
__device__ __forceinline__ void cpasync16(uint32_t dst, const void* src) {
    asm volatile("cp.async.cg.shared.global [%0], [%1], 16;\n" :: "r"(dst), "l"(src));
}
__device__ __forceinline__ void cp_commit() {
    asm volatile("cp.async.commit_group;\n" ::: "memory");
}

// D[m][n] = sum_k A[m][k]*B[n][k]  (fp16, K-contiguous rows)
// EPI: 0:+aux[n] fp16  1:+aux[m] fp16  2:exp(v*scale)+rowsum partials fp16
//      3:*aux[bz*NSP+m] fp16  4:+aux[m]+resid fp32
#define BM 128
#define BN 64
#define BK 64
#define RSTR 144                 // 64 halves (128B) + 16B pad
#define ATSZ (128 * RSTR)        // 18432
#define BTSZ (64 * RSTR)         // 9216
#define STGB (ATSZ + BTSZ)       // 27648
#define NSTAGE 2

template<int EPI>
__global__ void __launch_bounds__(128, 4)
gemm_h(const __half* __restrict__ A, const __half* __restrict__ B, void* __restrict__ Cv,
       int K, int lda, int ldb, int ldc, size_t sA, size_t sB, size_t sC,
       const float* __restrict__ aux, const float* __restrict__ resid,
       float* __restrict__ rsp, float scale) {
    extern __shared__ char dsm[];
    __shared__ float sm_rs[2][BM];
    int bz = blockIdx.z;
    A += sA * (size_t)bz;
    B += sB * (size_t)bz;

    const int m0 = blockIdx.y * BM;
    const int n0 = blockIdx.x * BN;
    int t = threadIdx.x, wid = t >> 5, lane = t & 31;
    int wm = wid >> 1, wn = wid & 1;     // 2 x 2 warps; warp tile 64x32
    int gr = lane >> 2, gc = lane & 3;

    uint32_t sbase = ((uint32_t)__cvta_generic_to_shared(dsm) + 127u) & ~127u;

    auto fill = [&](int kb, int stg) {
        uint32_t ab = sbase + stg * STGB;
        uint32_t bbs = ab + ATSZ;
        const __half* Ak = A + (size_t)m0 * lda + kb * BK;
        const __half* Bk = B + (size_t)n0 * ldb + kb * BK;
        #pragma unroll
        for (int i = 0; i < 8; i++) {        // A: 1024 16B-chunks
            int q = t + i * 128;
            int r = q >> 3, c = q & 7;
            cpasync16(ab + r * RSTR + c * 16, Ak + (size_t)r * lda + c * 8);
        }
        #pragma unroll
        for (int i = 0; i < 4; i++) {        // B: 512 chunks
            int q = t + i * 128;
            int r = q >> 3, c = q & 7;
            cpasync16(bbs + r * RSTR + c * 16, Bk + (size_t)r * ldb + c * 8);
        }
    };

    uint32_t a_off = (uint32_t)((wm * 64 + (lane & 15)) * RSTR + (lane >> 4) * 16);
    uint32_t b_off = (uint32_t)(ATSZ + (wn * 32 + (lane & 7) + ((lane >> 4) << 3)) * RSTR
                                + (((lane >> 3) & 1) * 16));

    float acc[4][4][4];
    #pragma unroll
    for (int i = 0; i < 4; i++)
        #pragma unroll
        for (int j = 0; j < 4; j++)
            #pragma unroll
            for (int r = 0; r < 4; r++) acc[i][j][r] = 0.f;

    const int nk = K / BK;
    fill(0, 0); cp_commit();

    for (int kb = 0; kb < nk; kb++) {
        asm volatile("cp.async.wait_group 0;\n" ::: "memory");
        __syncthreads();
        if (kb + 1 < nk) fill(kb + 1, (kb + 1) & 1);
        cp_commit();

        uint32_t abase = sbase + (kb & 1) * STGB + a_off;
        uint32_t bbase = sbase + (kb & 1) * STGB + b_off;

        #pragma unroll
        for (int kk = 0; kk < 4; kk++) {     // four k16 steps
            uint32_t af[4][4];
            #pragma unroll
            for (int mt = 0; mt < 4; mt++)
                ldmx4(af[mt], abase + mt * (16 * RSTR) + kk * 32);
            uint32_t bf[2][4];
            #pragma unroll
            for (int j = 0; j < 2; j++)
                ldmx4(bf[j], bbase + j * (16 * RSTR) + kk * 32);
            #pragma unroll
            for (int mt = 0; mt < 4; mt++)
                #pragma unroll
                for (int nt = 0; nt < 4; nt++)
                    mma_f16(acc[mt][nt], af[mt], &bf[nt >> 1][(nt & 1) * 2]);
        }
    }

    // ---- epilogue ----
    #pragma unroll
    for (int mt = 0; mt < 4; mt++) {
        int mA = m0 + wm * 64 + mt * 16 + gr;
        int mB = mA + 8;
        float bA = 0.f, bB = 0.f;
        if (EPI == 1 || EPI == 4) { bA = aux[mA]; bB = aux[mB]; }
        if (EPI == 3) { bA = aux[(size_t)bz * NSP + mA]; bB = aux[(size_t)bz * NSP + mB]; }
        float rsA = 0.f, rsB = 0.f;
        #pragma unroll
        for (int nt = 0; nt < 4; nt++) {
            int n = n0 + wn * 32 + nt * 8 + 2 * gc;
            float v0 = acc[mt][nt][0], v1 = acc[mt][nt][1];
            float v2 = acc[mt][nt][2], v3 = acc[mt][nt][3];
            if (EPI == 0) {
                float c0 = aux[n], c1 = aux[n + 1];
                v0 += c0; v1 += c1; v2 += c0; v3 += c1;
            }
            if (EPI == 1) { v0 += bA; v1 += bA; v2 += bB; v3 += bB; }
            if (EPI == 2) {
                v0 = __expf(v0 * scale); v1 = __expf(v1 * scale);
                v2 = __expf(v2 * scale); v3 = __expf(v3 * scale);
                rsA += v0 + v1; rsB += v2 + v3;
            }
            if (EPI == 3) { v0 *= bA; v1 *= bA; v2 *= bB; v3 *= bB; }
            if (EPI == 4) {
                const float* rp = resid + sC * (size_t)bz;
                float2 r0 = *reinterpret_cast<const float2*>(&rp[(size_t)mA * ldc + n]);
                float2 r1 = *reinterpret_cast<const float2*>(&rp[(size_t)mB * ldc + n]);
                v0 += bA + r0.x; v1 += bA + r0.y; v2 += bB + r1.x; v3 += bB + r1.y;
            }
            if (EPI == 4) {
                float* C = (float*)Cv + sC * (size_t)bz;
                *reinterpret_cast<float2*>(&C[(size_t)mA * ldc + n]) = make_float2(v0, v1);
                *reinterpret_cast<float2*>(&C[(size_t)mB * ldc + n]) = make_float2(v2, v3);
            } else {
                __half* C = (__half*)Cv + sC * (size_t)bz;
                *reinterpret_cast<__half2*>(&C[(size_t)mA * ldc + n]) = __floats2half2_rn(v0, v1);
                *reinterpret_cast<__half2*>(&C[(size_t)mB * ldc + n]) = __floats2half2_rn(v2, v3);
            }
        }
        if (EPI == 2) {
            // reduce over the 4 gc lanes (same rows)
            rsA += __shfl_xor_sync(0xffffffffu, rsA, 1);
            rsA += __shfl_xor_sync(0xffffffffu, rsA, 2);
            rsB += __shfl_xor_sync(0xffffffffu, rsB, 1);
            rsB += __shfl_xor_sync(0xffffffffu, rsB, 2);
            if (gc == 0) {
                sm_rs[wn][wm * 64 + mt * 16 + gr]     = rsA;
                sm_rs[wn][wm * 64 + mt * 16 + gr + 8] = rsB;
            }
        }
    }
    if (EPI == 2) {
        __syncthreads();
        // one partial per (row, jb); jb = blockIdx.x (64 j-tiles)
        rsp[((size_t)bz * NSP + m0 + t) * 64 + blockIdx.x] = sm_rs[0][t] + sm_rs[1][t];
    }
}

// ---------------- rowsum partial reduce -> 1/sum ----------------
__global__ void __launch_bounds__(256)
rsred_kernel(const float* __restrict__ rsp, float* __restrict__ inv) {
    int row = blockIdx.x * 8 + (threadIdx.x >> 5);
    int lane = threadIdx.x & 31;
    const float* p = rsp + (size_t)row * 64;
    float s = p[lane] + p[lane + 32];
    #pragma unroll
    for (int o = 16; o; o >>= 1) s += __shfl_xor_sync(0xffffffffu, s, o);
    if (lane == 0) inv[row] = 1.f / s;
}

// ---------------- launcher ----------------
extern "C" void kernel_launch(void* const* d_in, const int* in_sizes, int n_in,
                              void* d_out, int out_size) {
    const float* x    = (const float*)d_in[0];
    const float* gn_w = (const float*)d_in[1];
    const float* gn_b = (const float*)d_in[2];
    const float* wq   = (const float*)d_in[3];
    const float* bq   = (const float*)d_in[4];
    const float* wk   = (const float*)d_in[5];
    const float* bk   = (const float*)d_in[6];
    const float* wv   = (const float*)d_in[7];
    const float* bv   = (const float*)d_in[8];
    const float* wp   = (const float*)d_in[9];
    const float* bp   = (const float*)d_in[10];
    float* out = (float*)d_out;

    __half *hnT, *qkT, *v, *oT, *s, *wqk, *wvh, *wph;
    float *rs, *rsp, *bqk;
    cudaGetSymbolAddress((void**)&hnT, g_hnT);
    cudaGetSymbolAddress((void**)&qkT, g_qkT);
    cudaGetSymbolAddress((void**)&v,   g_v);
    cudaGetSymbolAddress((void**)&oT,  g_oT);
    cudaGetSymbolAddress((void**)&s,   g_s);
    cudaGetSymbolAddress((void**)&rs,  g_rs);
    cudaGetSymbolAddress((void**)&rsp, g_rsp);
    cudaGetSymbolAddress((void**)&wqk, g_wqk);
    cudaGetSymbolAddress((void**)&bqk, g_bqk);
    cudaGetSymbolAddress((void**)&wvh, g_wv);
    cudaGetSymbolAddress((void**)&wph, g_wp);

    const size_t CN  = (size_t)NSP * CDIM;
    const size_t QKN = (size_t)NSP * 1024;
    const size_t NN  = (size_t)NSP * NSP;
    const float attn_scale = 0.04419417382415922f;  // 1/sqrt(512)
    const int smem = NSTAGE * STGB + 256;           // 55552

    cudaFuncSetAttribute(gemm_h<0>, cudaFuncAttributeMaxDynamicSharedMemorySize, smem);
    cudaFuncSetAttribute(gemm_h<1>, cudaFuncAttributeMaxDynamicSharedMemorySize, smem);
    cudaFuncSetAttribute(gemm_h<2>, cudaFuncAttributeMaxDynamicSharedMemorySize, smem);
    cudaFuncSetAttribute(gemm_h<3>, cudaFuncAttributeMaxDynamicSharedMemorySize, smem);
    cudaFuncSetAttribute(gemm_h<4>, cudaFuncAttributeMaxDynamicSharedMemorySize, smem);

    w2h<<<(CDIM * CDIM + 255) / 256, 256>>>(wq, wk, wv, wp, bq, bk, wqk, wvh, wph, bqk);
    gn_kernel<<<BDIM * GROUPS, 512>>>(x, gn_w, gn_b, hnT);

    dim3 blk(128);
    // qkT[n][o] = sum_c hnT[n][c] wqk[o][c] + bqk[o]   M=NSP, N=1024
    gemm_h<0><<<dim3(1024 / BN, NSP / BM, BDIM), blk, smem>>>(
        hnT, wqk, qkT, CDIM, CDIM, CDIM, 1024, CN, 0, QKN, bqk, nullptr, nullptr, 0.f);
    // v[c][n] = sum_k wv[c][k] hnT[n][k] + bv[c]       M=CDIM, N=NSP
    gemm_h<1><<<dim3(NSP / BN, CDIM / BM, BDIM), blk, smem>>>(
        wvh, hnT, v, CDIM, CDIM, CDIM, NSP, 0, CN, CN, bv, nullptr, nullptr, 0.f);
    // s[i][j] = exp(sum_c qT[i][c] kT[j][c] * scale), rowsum partials
    gemm_h<2><<<dim3(NSP / BN, NSP / BM, BDIM), blk, smem>>>(
        qkT, qkT + CDIM, s, CDIM, 1024, 1024, NSP, QKN, QKN, NN,
        nullptr, nullptr, rsp, attn_scale);

    rsred_kernel<<<BDIM * NSP / 8, 256>>>(rsp, rs);

    // oT[i][c] = (sum_j s[i][j] v[c][j]) * rs[b][i]    M=NSP, N=CDIM
    gemm_h<3><<<dim3(CDIM / BN, NSP / BM, BDIM), blk, smem>>>(
        s, v, oT, NSP, NSP, NSP, CDIM, NN, CN, CN, rs, nullptr, nullptr, 0.f);
    // out[o][n] = sum_c wp[o][c] oT[n][c] + bp[o] + x  M=CDIM, N=NSP (fp32)
    gemm_h<4><<<dim3(NSP / BN, CDIM / BM, BDIM), blk, smem>>>(
        wph, oT, out, CDIM, CDIM, CDIM, NSP, 0, CN, CN, bp, x, nullptr, 0.f);
}

// round 13
// speedup vs baseline: 7.9768x; 1.0979x over previous
#include <cuda_runtime.h>
#include <cuda_fp16.h>
#include <cstdint>
#include <math.h>

#define BDIM 2
#define CDIM 512
#define NSP  4096
#define GROUPS 32
#define CPG  16

// ---- static scratch ----
__device__ __half g_hnT[(size_t)BDIM * NSP * CDIM];   // [b][n][c]
__device__ __half g_qkT[(size_t)BDIM * NSP * 1024];   // [b][n][q:512|k:512]
__device__ __half g_v  [(size_t)BDIM * CDIM * NSP];   // [b][c][n]
__device__ __half g_oT [(size_t)BDIM * NSP * CDIM];   // [b][n][c]
__device__ __half g_s  [(size_t)BDIM * NSP * NSP];    // [b][i][j] exp-scores
__device__ float  g_rsp[(size_t)BDIM * NSP * 32];     // row-sum partials [row][jb]
__device__ float  g_rs [(size_t)BDIM * NSP];          // 1/rowsum
__device__ float2 g_gnp[BDIM * GROUPS * 8];           // gn partial (sum, sumsq)
__device__ float2 g_gst[BDIM * GROUPS];               // gn (mean, rstd)
__device__ __half g_wqk[1024 * CDIM];
__device__ float  g_bqk[1024];
__device__ __half g_wv [CDIM * CDIM];
__device__ __half g_wp [CDIM * CDIM];

// ---------------- reductions ----------------
__device__ __forceinline__ float blockReduceSum(float v, float* sh) {
    #pragma unroll
    for (int o = 16; o; o >>= 1) v += __shfl_down_sync(0xffffffffu, v, o);
    int lane = threadIdx.x & 31, wid = threadIdx.x >> 5;
    if (lane == 0) sh[wid] = v;
    __syncthreads();
    int nw = blockDim.x >> 5;
    v = (threadIdx.x < nw) ? sh[threadIdx.x] : 0.f;
    if (wid == 0) {
        #pragma unroll
        for (int o = 16; o; o >>= 1) v += __shfl_down_sync(0xffffffffu, v, o);
    }
    return v;
}

// ---------------- weights fp32->fp16 (+ q|k concat) ----------------
__global__ void __launch_bounds__(256)
w2h(const float* __restrict__ wq, const float* __restrict__ wk,
    const float* __restrict__ wv, const float* __restrict__ wp,
    const float* __restrict__ bq, const float* __restrict__ bk,
    __half* __restrict__ Wqk, __half* __restrict__ Wv,
    __half* __restrict__ Wp, float* __restrict__ Bqk) {
    int i = blockIdx.x * 256 + threadIdx.x;
    if (i < CDIM * CDIM) {
        Wqk[i] = __float2half_rn(wq[i]);
        Wqk[i + CDIM * CDIM] = __float2half_rn(wk[i]);
        Wv[i] = __float2half_rn(wv[i]);
        Wp[i] = __float2half_rn(wp[i]);
    }
    if (i < CDIM) { Bqk[i] = bq[i]; Bqk[i + CDIM] = bk[i]; }
}

// ---------------- GroupNorm pass 1: partial sums (512 CTAs) ----------------
__global__ void __launch_bounds__(256)
gn_stats1(const float* __restrict__ x, float2* __restrict__ gnp) {
    __shared__ float sh[32];
    int blk = blockIdx.x;
    int chunk = blk & 7, bg = blk >> 3;
    const float* xp = x + (size_t)bg * CPG * NSP + chunk * 512;
    const float4* xp4 = reinterpret_cast<const float4*>(xp);
    int t = threadIdx.x;
    float s = 0.f, ss = 0.f;
    for (int i = t; i < 2048; i += 256) {
        int c = i >> 7, n4 = i & 127;
        float4 v = xp4[c * (NSP / 4) + n4];
        s  += v.x + v.y + v.z + v.w;
        ss += v.x * v.x + v.y * v.y + v.z * v.z + v.w * v.w;
    }
    float ts = blockReduceSum(s, sh);
    __syncthreads();
    float tss = blockReduceSum(ss, sh);
    if (t == 0) gnp[blk] = make_float2(ts, tss);
}

// ---------------- GroupNorm pass 2: reduce to (mean, rstd) ----------------
__global__ void __launch_bounds__(32)
gn_stats2(const float2* __restrict__ gnp, float2* __restrict__ gst) {
    int lane = threadIdx.x;
    float s = 0.f, ss = 0.f;
    if (lane < 8) {
        float2 p = gnp[blockIdx.x * 8 + lane];
        s = p.x; ss = p.y;
    }
    #pragma unroll
    for (int o = 4; o; o >>= 1) {
        s  += __shfl_down_sync(0xffffffffu, s, o);
        ss += __shfl_down_sync(0xffffffffu, ss, o);
    }
    if (lane == 0) {
        float mean = s / 65536.f;
        float var  = ss / 65536.f - mean * mean;
        gst[blockIdx.x] = make_float2(mean, rsqrtf(var + 1e-6f));
    }
}

// ---------------- GroupNorm pass 3: normalize + transpose (512 CTAs) ----------------
__global__ void __launch_bounds__(256)
gn_norm(const float* __restrict__ x, const float* __restrict__ w,
        const float* __restrict__ bb, const float2* __restrict__ gst,
        __half* __restrict__ hnT) {
    __shared__ float tile[16][129];
    int blk = blockIdx.x;
    int chunk = blk & 7, bg = blk >> 3;
    int b = bg / GROUPS, g = bg % GROUPS;
    const float* xp = x + (size_t)bg * CPG * NSP;
    float2 st = gst[bg];
    float mean = st.x, rstd = st.y;
    int t = threadIdx.x;

    float sc[1], bi[1];  // per-thread c varies; just read in loop
    __half* hT = hnT + (size_t)b * NSP * CDIM;
    (void)sc; (void)bi;

    for (int sub = 0; sub < 4; sub++) {
        int n0 = chunk * 512 + sub * 128;
        #pragma unroll
        for (int e = 0; e < 8; e++) {
            int idx = e * 256 + t;
            int c = idx >> 7, n = idx & 127;
            float v = xp[(size_t)c * NSP + n0 + n];
            tile[c][n] = (v - mean) * rstd * w[g * CPG + c] + bb[g * CPG + c];
        }
        __syncthreads();
        int n = t >> 1, ch = (t & 1) * 8;
        __half2 h0 = __floats2half2_rn(tile[ch + 0][n], tile[ch + 1][n]);
        __half2 h1 = __floats2half2_rn(tile[ch + 2][n], tile[ch + 3][n]);
        __half2 h2 = __floats2half2_rn(tile[ch + 4][n], tile[ch + 5][n]);
        __half2 h3 = __floats2half2_rn(tile[ch + 6][n], tile[ch + 7][n]);
        uint4 pk;
        pk.x = *reinterpret_cast<uint32_t*>(&h0);
        pk.y = *reinterpret_cast<uint32_t*>(&h1);
        pk.z = *reinterpret_cast<uint32_t*>(&h2);
        pk.w = *reinterpret_cast<uint32_t*>(&h3);
        *reinterpret_cast<uint4*>(&hT[(size_t)(n0 + n) * CDIM + g * CPG + ch]) = pk;
        __syncthreads();
    }
}

// ---------------- fp16 tensor-core GEMM, 256thr / 128x128 / BK=64 ----------------
__device__ __forceinline__ void mma_f16(float* c, const uint32_t* a, const uint32_t* b) {
    asm volatile(
        "mma.sync.aligned.m16n8k16.row.col.f32.f16.f16.f32 "
        "{%0,%1,%2,%3}, {%4,%5,%6,%7}, {%8,%9}, {%0,%1,%2,%3};"
        : "+f"(c[0]), "+f"(c[1]), "+f"(c[2]), "+f"(c[3])
        : "r"(a[0]), "r"(a[1]), "r"(a[2]), "r"(a[3]), "r"(b[0]), "r"(b[1]));
}
__device__ __forceinline__ void ldmx4(uint32_t* r, uint32_t addr) {
    asm volatile("ldmatrix.sync.aligned.m8n8.x4.shared.b16 {%0,%1,%2,%3}, [%4];"
                 : "=r"(r[0]), "=r"(r[1]), "=r"(r[2]), "=r"(r[3]) : "r"(addr));
}
__device__ __forceinline__ void cpasync16(uint32_t dst, const void* src) {
    asm volatile("cp.async.cg.shared.global [%0], [%1], 16;\n" :: "r"(dst), "l"(src));
}
__device__ __forceinline__ void cp_commit() {
    asm volatile("cp.async.commit_group;\n" ::: "memory");
}

// D[m][n] = sum_k A[m][k]*B[n][k]  (fp16, K-contiguous rows)
// EPI: 0:+aux[n] fp16  1:+aux[m] fp16  2:exp(v*scale)+rowsum partials fp16
//      3:*aux[bz*NSP+m] fp16  4:+aux[m]+resid fp32
#define BM 128
#define BN 128
#define BK 64
#define RSTR 144
#define ATSZ (128 * RSTR)        // 18432
#define BTSZ (128 * RSTR)        // 18432
#define STGB (ATSZ + BTSZ)       // 36864
#define NSTAGE 2

template<int EPI>
__global__ void __launch_bounds__(256, 2)
gemm_h(const __half* __restrict__ A, const __half* __restrict__ B, void* __restrict__ Cv,
       int K, int lda, int ldb, int ldc, size_t sA, size_t sB, size_t sC,
       const float* __restrict__ aux, const float* __restrict__ resid,
       float* __restrict__ rsp, float scale) {
    extern __shared__ char dsm[];
    __shared__ float sm_rs[4][BM];
    int bz = blockIdx.z;
    A += sA * (size_t)bz;
    B += sB * (size_t)bz;

    const int m0 = blockIdx.y * BM;
    const int n0 = blockIdx.x * BN;
    int t = threadIdx.x, wid = t >> 5, lane = t & 31;
    int wm = wid >> 2, wn = wid & 3;     // 2 x 4 warps; warp tile 64x32
    int gr = lane >> 2, gc = lane & 3;

    uint32_t sbase = ((uint32_t)__cvta_generic_to_shared(dsm) + 127u) & ~127u;

    auto fill = [&](int kb, int stg) {
        uint32_t ab = sbase + stg * STGB;
        uint32_t bbs = ab + ATSZ;
        const __half* Ak = A + (size_t)m0 * lda + kb * BK;
        const __half* Bk = B + (size_t)n0 * ldb + kb * BK;
        #pragma unroll
        for (int i = 0; i < 4; i++) {        // A: 1024 16B-chunks
            int q = t + i * 256;
            int r = q >> 3, c = q & 7;
            cpasync16(ab + r * RSTR + c * 16, Ak + (size_t)r * lda + c * 8);
        }
        #pragma unroll
        for (int i = 0; i < 4; i++) {        // B: 1024 chunks
            int q = t + i * 256;
            int r = q >> 3, c = q & 7;
            cpasync16(bbs + r * RSTR + c * 16, Bk + (size_t)r * ldb + c * 8);
        }
    };

    uint32_t a_off = (uint32_t)((wm * 64 + (lane & 15)) * RSTR + (lane >> 4) * 16);
    uint32_t b_off = (uint32_t)(ATSZ + (wn * 32 + (lane & 7) + ((lane >> 4) << 3)) * RSTR
                                + (((lane >> 3) & 1) * 16));

    float acc[4][4][4];
    #pragma unroll
    for (int i = 0; i < 4; i++)
        #pragma unroll
        for (int j = 0; j < 4; j++)
            #pragma unroll
            for (int r = 0; r < 4; r++) acc[i][j][r] = 0.f;

    const int nk = K / BK;
    fill(0, 0); cp_commit();

    for (int kb = 0; kb < nk; kb++) {
        asm volatile("cp.async.wait_group 0;\n" ::: "memory");
        __syncthreads();

        uint32_t abase = sbase + (kb & 1) * STGB + a_off;
        uint32_t bbase = sbase + (kb & 1) * STGB + b_off;

        #pragma unroll
        for (int kk = 0; kk < 4; kk++) {     // four k16 steps
            uint32_t af[4][4];
            #pragma unroll
            for (int mt = 0; mt < 4; mt++)
                ldmx4(af[mt], abase + mt * (16 * RSTR) + kk * 32);
            uint32_t bf[2][4];
            #pragma unroll
            for (int j = 0; j < 2; j++)
                ldmx4(bf[j], bbase + j * (16 * RSTR) + kk * 32);
            #pragma unroll
            for (int mt = 0; mt < 4; mt++)
                #pragma unroll
                for (int nt = 0; nt < 4; nt++)
                    mma_f16(acc[mt][nt], af[mt], &bf[nt >> 1][(nt & 1) * 2]);
            if (kk == 0) {                   // mid-block prefetch of next stage
                if (kb + 1 < nk) fill(kb + 1, (kb + 1) & 1);
                cp_commit();
            }
        }
    }

    // ---- epilogue ----
    #pragma unroll
    for (int mt = 0; mt < 4; mt++) {
        int mA = m0 + wm * 64 + mt * 16 + gr;
        int mB = mA + 8;
        float bA = 0.f, bB = 0.f;
        if (EPI == 1 || EPI == 4) { bA = aux[mA]; bB = aux[mB]; }
        if (EPI == 3) { bA = aux[(size_t)bz * NSP + mA]; bB = aux[(size_t)bz * NSP + mB]; }
        float rsA = 0.f, rsB = 0.f;
        #pragma unroll
        for (int nt = 0; nt < 4; nt++) {
            int n = n0 + wn * 32 + nt * 8 + 2 * gc;
            float v0 = acc[mt][nt][0], v1 = acc[mt][nt][1];
            float v2 = acc[mt][nt][2], v3 = acc[mt][nt][3];
            if (EPI == 0) {
                float c0 = aux[n], c1 = aux[n + 1];
                v0 += c0; v1 += c1; v2 += c0; v3 += c1;
            }
            if (EPI == 1) { v0 += bA; v1 += bA; v2 += bB; v3 += bB; }
            if (EPI == 2) {
                v0 = __expf(v0 * scale); v1 = __expf(v1 * scale);
                v2 = __expf(v2 * scale); v3 = __expf(v3 * scale);
                rsA += v0 + v1; rsB += v2 + v3;
            }
            if (EPI == 3) { v0 *= bA; v1 *= bA; v2 *= bB; v3 *= bB; }
            if (EPI == 4) {
                const float* rp = resid + sC * (size_t)bz;
                float2 r0 = *reinterpret_cast<const float2*>(&rp[(size_t)mA * ldc + n]);
                float2 r1 = *reinterpret_cast<const float2*>(&rp[(size_t)mB * ldc + n]);
                v0 += bA + r0.x; v1 += bA + r0.y; v2 += bB + r1.x; v3 += bB + r1.y;
            }
            if (EPI == 4) {
                float* C = (float*)Cv + sC * (size_t)bz;
                *reinterpret_cast<float2*>(&C[(size_t)mA * ldc + n]) = make_float2(v0, v1);
                *reinterpret_cast<float2*>(&C[(size_t)mB * ldc + n]) = make_float2(v2, v3);
            } else {
                __half* C = (__half*)Cv + sC * (size_t)bz;
                *reinterpret_cast<__half2*>(&C[(size_t)mA * ldc + n]) = __floats2half2_rn(v0, v1);
                *reinterpret_cast<__half2*>(&C[(size_t)mB * ldc + n]) = __floats2half2_rn(v2, v3);
            }
        }
        if (EPI == 2) {
            rsA += __shfl_xor_sync(0xffffffffu, rsA, 1);
            rsA += __shfl_xor_sync(0xffffffffu, rsA, 2);
            rsB += __shfl_xor_sync(0xffffffffu, rsB, 1);
            rsB += __shfl_xor_sync(0xffffffffu, rsB, 2);
            if (gc == 0) {
                sm_rs[wn][wm * 64 + mt * 16 + gr]     = rsA;
                sm_rs[wn][wm * 64 + mt * 16 + gr + 8] = rsB;
            }
        }
    }
    if (EPI == 2) {
        __syncthreads();
        if (t < BM)
            rsp[((size_t)bz * NSP + m0 + t) * 32 + blockIdx.x] =
                sm_rs[0][t] + sm_rs[1][t] + sm_rs[2][t] + sm_rs[3][t];
    }
}

// ---------------- rowsum partial reduce -> 1/sum ----------------
__global__ void __launch_bounds__(256)
rsred_kernel(const float* __restrict__ rsp, float* __restrict__ inv) {
    int row = blockIdx.x * 8 + (threadIdx.x >> 5);
    int lane = threadIdx.x & 31;
    float s = rsp[(size_t)row * 32 + lane];
    #pragma unroll
    for (int o = 16; o; o >>= 1) s += __shfl_xor_sync(0xffffffffu, s, o);
    if (lane == 0) inv[row] = 1.f / s;
}

// ---------------- launcher ----------------
extern "C" void kernel_launch(void* const* d_in, const int* in_sizes, int n_in,
                              void* d_out, int out_size) {
    const float* x    = (const float*)d_in[0];
    const float* gn_w = (const float*)d_in[1];
    const float* gn_b = (const float*)d_in[2];
    const float* wq   = (const float*)d_in[3];
    const float* bq   = (const float*)d_in[4];
    const float* wk   = (const float*)d_in[5];
    const float* bk   = (const float*)d_in[6];
    const float* wv   = (const float*)d_in[7];
    const float* bv   = (const float*)d_in[8];
    const float* wp   = (const float*)d_in[9];
    const float* bp   = (const float*)d_in[10];
    float* out = (float*)d_out;

    __half *hnT, *qkT, *v, *oT, *s, *wqk, *wvh, *wph;
    float *rs, *rsp, *bqk;
    float2 *gnp, *gst;
    cudaGetSymbolAddress((void**)&hnT, g_hnT);
    cudaGetSymbolAddress((void**)&qkT, g_qkT);
    cudaGetSymbolAddress((void**)&v,   g_v);
    cudaGetSymbolAddress((void**)&oT,  g_oT);
    cudaGetSymbolAddress((void**)&s,   g_s);
    cudaGetSymbolAddress((void**)&rs,  g_rs);
    cudaGetSymbolAddress((void**)&rsp, g_rsp);
    cudaGetSymbolAddress((void**)&gnp, g_gnp);
    cudaGetSymbolAddress((void**)&gst, g_gst);
    cudaGetSymbolAddress((void**)&wqk, g_wqk);
    cudaGetSymbolAddress((void**)&bqk, g_bqk);
    cudaGetSymbolAddress((void**)&wvh, g_wv);
    cudaGetSymbolAddress((void**)&wph, g_wp);

    const size_t CN  = (size_t)NSP * CDIM;
    const size_t QKN = (size_t)NSP * 1024;
    const size_t NN  = (size_t)NSP * NSP;
    const float attn_scale = 0.04419417382415922f;  // 1/sqrt(512)
    const int smem = NSTAGE * STGB + 256;           // 73984

    cudaFuncSetAttribute(gemm_h<0>, cudaFuncAttributeMaxDynamicSharedMemorySize, smem);
    cudaFuncSetAttribute(gemm_h<1>, cudaFuncAttributeMaxDynamicSharedMemorySize, smem);
    cudaFuncSetAttribute(gemm_h<2>, cudaFuncAttributeMaxDynamicSharedMemorySize, smem);
    cudaFuncSetAttribute(gemm_h<3>, cudaFuncAttributeMaxDynamicSharedMemorySize, smem);
    cudaFuncSetAttribute(gemm_h<4>, cudaFuncAttributeMaxDynamicSharedMemorySize, smem);

    w2h<<<(CDIM * CDIM + 255) / 256, 256>>>(wq, wk, wv, wp, bq, bk, wqk, wvh, wph, bqk);
    gn_stats1<<<BDIM * GROUPS * 8, 256>>>(x, gnp);
    gn_stats2<<<BDIM * GROUPS, 32>>>(gnp, gst);
    gn_norm<<<BDIM * GROUPS * 8, 256>>>(x, gn_w, gn_b, gst, hnT);

    dim3 blk(256);
    // qkT[n][o] = sum_c hnT[n][c] wqk[o][c] + bqk[o]   M=NSP, N=1024
    gemm_h<0><<<dim3(1024 / BN, NSP / BM, BDIM), blk, smem>>>(
        hnT, wqk, qkT, CDIM, CDIM, CDIM, 1024, CN, 0, QKN, bqk, nullptr, nullptr, 0.f);
    // v[c][n] = sum_k wv[c][k] hnT[n][k] + bv[c]       M=CDIM, N=NSP
    gemm_h<1><<<dim3(NSP / BN, CDIM / BM, BDIM), blk, smem>>>(
        wvh, hnT, v, CDIM, CDIM, CDIM, NSP, 0, CN, CN, bv, nullptr, nullptr, 0.f);
    // s[i][j] = exp(sum_c qT[i][c] kT[j][c] * scale), rowsum partials
    gemm_h<2><<<dim3(NSP / BN, NSP / BM, BDIM), blk, smem>>>(
        qkT, qkT + CDIM, s, CDIM, 1024, 1024, NSP, QKN, QKN, NN,
        nullptr, nullptr, rsp, attn_scale);

    rsred_kernel<<<BDIM * NSP / 8, 256>>>(rsp, rs);

    // oT[i][c] = (sum_j s[i][j] v[c][j]) * rs[b][i]    M=NSP, N=CDIM
    gemm_h<3><<<dim3(CDIM / BN, NSP / BM, BDIM), blk, smem>>>(
        s, v, oT, NSP, NSP, NSP, CDIM, NN, CN, CN, rs, nullptr, nullptr, 0.f);
    // out[o][n] = sum_c wp[o][c] oT[n][c] + bp[o] + x  M=CDIM, N=NSP (fp32)
    gemm_h<4><<<dim3(NSP / BN, CDIM / BM, BDIM), blk, smem>>>(
        wph, oT, out, CDIM, CDIM, CDIM, NSP, 0, CN, CN, bp, x, nullptr, 0.f);
}